// round 15
// baseline (speedup 1.0000x reference)
#include <cuda_runtime.h>
#include <cuda_fp16.h>
#include <math.h>

#define CDIV(a,b) (((a)+(b)-1)/(b))

namespace {
constexpr int NNODES = 50000;
constexpr int NEDGES = 300000;
constexpr int NTOT   = 100000;
constexpr int NE2    = 2 * NEDGES;      // 600000
constexpr int SCAN_B = 98;              // CDIV(NTOT, 1024)
constexpr int SMEM_BYTES = (2 * 128 * 36 + 2 * 32 * 72) * 4;   // 55296 (x3 CTAs = 166KB)
}

// ------------------------- static device scratch (zero-initialized at load) ----------
__device__ float    g_f0 [16777216];   // (2,256,32^3) conv0 out fp32
__device__ unsigned g_f0h[8388608];    // (2,32^3,128u) fp16x2 after bn+relu, (b,s,c)
__device__ float    g_f1 [4194304];    // (2,16^3,512) conv1 out fp32
__device__ unsigned g_f1h[2097152];    // (2,16^3,256u) fp16x2
__device__ float    g_f2 [4194304];    // conv2 out fp32
__device__ unsigned g_f2h[2097152];    // fp16x2
__device__ unsigned g_w1p[4194304];    // w1 packed (K2=8192, 512) fp16x2
__device__ unsigned g_w2p[3538944];    // w2 packed (K2=6912, 512) fp16x2
__device__ unsigned g_wfeat1p[262144]; // (K2=256, 1024) fp16x2
__device__ float    g_wpos1[3072];     // (3,1024) fp32 pos rows
__device__ float    g_bias1[1024];
__device__ unsigned g_wcat2p[65536];   // (K2=128, 512) fp16x2
__device__ float    g_bias2[512];
__device__ unsigned g_m1wp[4096];      // (K2=64, 64) fp16x2
__device__ float    g_voxout[8388608]; // (8192,1024)
__device__ float    g_kqvs1[102400000];// (100000,1024)
__device__ unsigned g_h1h[12800000];   // (100000,128u) fp16x2
__device__ float    g_kqvs2[51200000]; // (100000,512)
__device__ unsigned g_h2h[6400000];    // (100000,64u) fp16x2
__device__ float    g_h3[6400000];     // (100000,64)
__device__ float    g_scale[512];
__device__ float    g_shift[512];
// BN stat accumulators. INVARIANT: zero at entry of every kernel_launch call.
__device__ float    g_cs [512];
__device__ float    g_cs2[512];
// CSR. INVARIANT: g_deg zero at entry (self-cleaned by scan1).
__device__ int      g_deg[100352];
__device__ int      g_scan[100352];
__device__ int      g_bsum[SCAN_B];
__device__ int      g_off[100001];
__device__ int      g_cur[100000];
__device__ int      g_srcs[600000];

__device__ __forceinline__ unsigned pack2(float a, float b) {
    __half2 h = __floats2half2_rn(a, b);
    return *reinterpret_cast<unsigned*>(&h);
}

__device__ __forceinline__ void cpa16(void* dst, const void* src, bool pred) {
    unsigned d = (unsigned)__cvta_generic_to_shared(dst);
    int sz = pred ? 16 : 0;
    asm volatile("cp.async.cg.shared.global [%0], [%1], 16, %2;\n" :: "r"(d), "l"(src), "r"(sz));
}
__device__ __forceinline__ void cpa4(void* dst, const void* src, bool pred) {
    unsigned d = (unsigned)__cvta_generic_to_shared(dst);
    int sz = pred ? 4 : 0;
    asm volatile("cp.async.ca.shared.global [%0], [%1], 4, %2;\n" :: "r"(d), "l"(src), "r"(sz));
}

// ------------------------- conv0: direct 3x3x3, C_in=4 + fused BN stats --------------
__global__ void conv0_kernel(const float* __restrict__ x, const float* __restrict__ w0) {
    __shared__ float ws[108];
    __shared__ float r1[256], r2[256];
    int co = blockIdx.y, b = blockIdx.z;
    if (threadIdx.x < 108) ws[threadIdx.x] = w0[co * 108 + threadIdx.x];
    __syncthreads();
    int s = blockIdx.x * 256 + threadIdx.x;
    int z = s >> 10, y = (s >> 5) & 31, xx = s & 31;
    float acc = 0.f;
    #pragma unroll
    for (int ci = 0; ci < 4; ci++) {
        const float* xb = x + ((size_t)(b * 4 + ci) << 15);
        const float* wc = ws + ci * 27;
        #pragma unroll
        for (int kd = 0; kd < 3; kd++) {
            int id = z + kd - 1;
            if ((unsigned)id > 31u) continue;
            #pragma unroll
            for (int kh = 0; kh < 3; kh++) {
                int ih = y + kh - 1;
                if ((unsigned)ih > 31u) continue;
                #pragma unroll
                for (int kw = 0; kw < 3; kw++) {
                    int iw = xx + kw - 1;
                    if ((unsigned)iw > 31u) continue;
                    acc = fmaf(xb[(id << 10) + (ih << 5) + iw], wc[kd * 9 + kh * 3 + kw], acc);
                }
            }
        }
    }
    g_f0[(((size_t)((b << 8) + co)) << 15) + s] = acc;
    int tid = threadIdx.x;
    r1[tid] = acc; r2[tid] = acc * acc; __syncthreads();
    for (int o = 128; o; o >>= 1) {
        if (tid < o) { r1[tid] += r1[tid + o]; r2[tid] += r2[tid + o]; }
        __syncthreads();
    }
    if (tid == 0) {
        atomicAdd(&g_cs[co],  r1[0]);
        atomicAdd(&g_cs2[co], r2[0]);
    }
}

// bn+relu+transpose: f0 (b,c,s) fp32 -> f0h (b,s,c/2) fp16x2
__global__ void bn0_tr_kernel(const float* __restrict__ gm, const float* __restrict__ bt) {
    __shared__ float tile[32][33];
    __shared__ float scw[32], shw[32];
    int b = blockIdx.z, c0 = blockIdx.y * 32, s0 = blockIdx.x * 32;
    int x = threadIdx.x, y = threadIdx.y;      // 32 x 8
    if (y == 0) {
        int c = c0 + x;
        float inv = 1.f / 65536.f;
        float mean = g_cs[c] * inv;
        float var  = g_cs2[c] * inv - mean * mean;
        float sc = gm[c] * rsqrtf(var + 1e-5f);
        scw[x] = sc; shw[x] = bt[c] - mean * sc;
    }
    __syncthreads();
    for (int i = y; i < 32; i += 8) {
        float v = g_f0[(((size_t)((b << 8) + c0 + i)) << 15) + s0 + x];
        tile[i][x] = fmaxf(v * scw[i] + shw[i], 0.f);
    }
    __syncthreads();
    if (x < 16) {
        for (int i = y; i < 32; i += 8) {
            int s = s0 + i;
            g_f0h[((size_t)(b << 15) + s) * 128 + (c0 >> 1) + x] =
                pack2(tile[2 * x][i], tile[2 * x + 1][i]);
        }
    }
}

__global__ void reset_cs() {
    int c = threadIdx.x + blockIdx.x * 256;   // 512
    g_cs[c] = 0.f; g_cs2[c] = 0.f;
}

// ------------------------- fast BN stats, layout (rows, 512) -------------------------
__global__ void bn_stats_fast(const float* __restrict__ x, int rows) {
    int tid = threadIdx.x;               // 0..127
    int rpb = rows / gridDim.x;
    int r0 = blockIdx.x * rpb;
    float a1x = 0.f, a1y = 0.f, a1z = 0.f, a1w = 0.f;
    float a2x = 0.f, a2y = 0.f, a2z = 0.f, a2w = 0.f;
    const float4* xr = (const float4*)x;
    for (int r = r0; r < r0 + rpb; r++) {
        float4 v = xr[(size_t)r * 128 + tid];
        a1x += v.x; a1y += v.y; a1z += v.z; a1w += v.w;
        a2x += v.x * v.x; a2y += v.y * v.y; a2z += v.z * v.z; a2w += v.w * v.w;
    }
    int c = tid * 4;
    atomicAdd(&g_cs[c + 0], a1x); atomicAdd(&g_cs2[c + 0], a2x);
    atomicAdd(&g_cs[c + 1], a1y); atomicAdd(&g_cs2[c + 1], a2y);
    atomicAdd(&g_cs[c + 2], a1z); atomicAdd(&g_cs2[c + 2], a2z);
    atomicAdd(&g_cs[c + 3], a1w); atomicAdd(&g_cs2[c + 3], a2w);
}

__global__ void bn_final_rc(const float* __restrict__ gm, const float* __restrict__ bt,
                            float invRows) {
    int c = blockIdx.x * 256 + threadIdx.x;   // 512
    float mean = g_cs[c] * invRows;
    float var  = g_cs2[c] * invRows - mean * mean;
    float sc = gm[c] * rsqrtf(var + 1e-5f);
    g_scale[c] = sc;
    g_shift[c] = bt[c] - mean * sc;
    g_cs[c] = 0.f; g_cs2[c] = 0.f;            // self-clean for next use
}

// bn-apply -> fp16x2, layout (rows, C) float4 in, uint2 out
__global__ void bn_apply_rc_h(const float* __restrict__ x, unsigned* __restrict__ o,
                              int C, int n4, int do_relu) {
    int i = blockIdx.x * blockDim.x + threadIdx.x;
    if (i >= n4) return;
    int c = (i * 4) % C;
    float4 v = ((const float4*)x)[i];
    v.x = v.x * g_scale[c]     + g_shift[c];
    v.y = v.y * g_scale[c + 1] + g_shift[c + 1];
    v.z = v.z * g_scale[c + 2] + g_shift[c + 2];
    v.w = v.w * g_scale[c + 3] + g_shift[c + 3];
    if (do_relu) {
        v.x = fmaxf(v.x, 0.f); v.y = fmaxf(v.y, 0.f);
        v.z = fmaxf(v.z, 0.f); v.w = fmaxf(v.w, 0.f);
    }
    uint2 u; u.x = pack2(v.x, v.y); u.y = pack2(v.z, v.w);
    ((uint2*)o)[i] = u;
}

// ------------------------- weight prep (fp16x2 packed along K) -------------------------
__global__ void pack_w1(const float* __restrict__ w1) {
    int i = blockIdx.x * blockDim.x + threadIdx.x;   // k2 * 512 + co, k2 < 8192
    if (i >= 8192 * 512) return;
    int k2 = i >> 9, co = i & 511;
    int r = k2 >> 7, ci = (k2 & 127) * 2;
    size_t base = (size_t)co * 16384 + (size_t)ci * 64 + r;
    g_w1p[i] = pack2(w1[base], w1[base + 64]);
}

__global__ void pack_w2(const float* __restrict__ w2) {
    int i = blockIdx.x * blockDim.x + threadIdx.x;   // k2 * 512 + co, k2 < 6912
    if (i >= 6912 * 512) return;
    int k2 = i >> 9, co = i & 511;
    int r = k2 >> 8, ci = (k2 & 255) * 2;
    size_t base = (size_t)co * 13824 + (size_t)ci * 27 + r;
    g_w2p[i] = pack2(w2[base], w2[base + 27]);
}

__global__ void pack_cols(const float* __restrict__ src, unsigned* __restrict__ dst,
                          int rowOff, int K2, int F, int off, int Nout) {
    int i = blockIdx.x * blockDim.x + threadIdx.x;
    if (i >= K2 * F) return;
    int k2 = i / F, f = i - k2 * F;
    float a = src[(size_t)(2 * k2 + rowOff) * F + f];
    float b = src[(size_t)(2 * k2 + 1 + rowOff) * F + f];
    dst[(size_t)k2 * Nout + off + f] = pack2(a, b);
}

__global__ void copy_rows(const float* __restrict__ src, float* __restrict__ dst,
                          int rows, int F, int off, int Nout) {
    int i = blockIdx.x * blockDim.x + threadIdx.x;
    if (i >= rows * F) return;
    int k = i / F, f = i - k * F;
    dst[(size_t)k * Nout + off + f] = src[(size_t)k * F + f];
}

__global__ void build_bias(const float* __restrict__ src, float* __restrict__ dst,
                           int off, int F, int Nout) {
    int i = blockIdx.x * blockDim.x + threadIdx.x;
    if (i >= Nout) return;
    dst[i] = (i >= off && i < off + F) ? src[i - off] : 0.f;
}

// ------------------------- CSR build -------------------------
__global__ void hist_kernel(const int* __restrict__ ei) {
    int j = blockIdx.x * blockDim.x + threadIdx.x;
    if (j >= NE2) return;
    int b = (j >= NEDGES) ? 1 : 0;
    int e = j - b * NEDGES;
    int dst = __ldg(ei + NEDGES + e) + b * NNODES;
    atomicAdd(&g_deg[dst], 1);
}

__global__ void scan1_kernel() {
    __shared__ int tmp[1024];
    int tid = threadIdx.x;
    int gid = blockIdx.x * 1024 + tid;
    int v = (gid < NTOT) ? g_deg[gid] : 0;
    g_deg[gid] = 0;                      // self-clean
    tmp[tid] = v;
    __syncthreads();
    for (int o = 1; o < 1024; o <<= 1) {
        int t = (tid >= o) ? tmp[tid - o] : 0;
        __syncthreads();
        tmp[tid] += t;
        __syncthreads();
    }
    g_scan[gid] = tmp[tid] - v;
    if (tid == 1023) g_bsum[blockIdx.x] = tmp[1023];
}

__global__ void scan2_kernel() {
    if (threadIdx.x == 0) {
        int run = 0;
        for (int i = 0; i < SCAN_B; i++) { int t = g_bsum[i]; g_bsum[i] = run; run += t; }
        g_off[NTOT] = NE2;
    }
}

__global__ void scan3_kernel() {
    int gid = blockIdx.x * 1024 + threadIdx.x;
    if (gid >= NTOT) return;
    int o = g_scan[gid] + g_bsum[blockIdx.x];
    g_off[gid] = o;
    g_cur[gid] = o;
}

__global__ void fill_kernel(const int* __restrict__ ei) {
    int j = blockIdx.x * blockDim.x + threadIdx.x;
    if (j >= NE2) return;
    int b = (j >= NEDGES) ? 1 : 0;
    int e = j - b * NEDGES;
    int src = __ldg(ei + e) + b * NNODES;
    int dst = __ldg(ei + NEDGES + e) + b * NNODES;
    int pos = atomicAdd(&g_cur[dst], 1);
    g_srcs[pos] = src;
}

// -------- fp16 tensor-core GEMM (m16n8k16, 128x64 tile, cp.async 2-stage, 3 CTAs/SM) ------
// Warp grid 4x2, warp tile 32x32 (mt=2 x 16, nt=4 x 8).
#define ASD(s,m,k) sA[(s) * 4608 + (m) * 36 + (k)]
#define BSD(s,k,n) sB[(s) * 2304 + (k) * 72 + (n)]
template<int MODE>
__global__ void __launch_bounds__(256, 3)
mma_gemm(const unsigned* __restrict__ A, const unsigned* __restrict__ Bm,
         float* __restrict__ C, int M, int N, int K2, int lda,
         const float* __restrict__ bias, int do_relu) {
    extern __shared__ unsigned sm_raw[];
    unsigned* sA = sm_raw;            // 2 * 128 * 36
    unsigned* sB = sm_raw + 9216;     // 2 * 32 * 72
    int tid = threadIdx.x;
    int bm = blockIdx.y * 128, bn = blockIdx.x * 64;
    int warp = tid >> 5, lane = tid & 31;
    int wm = warp & 3, wn = warp >> 2;
    int g = lane >> 2, t4 = lane & 3;

    float c[2][4][4];
    #pragma unroll
    for (int i = 0; i < 2; i++)
        #pragma unroll
        for (int j = 0; j < 4; j++)
            #pragma unroll
            for (int r = 0; r < 4; r++) c[i][j][r] = 0.f;

    int ntiles = K2 >> 5;

    auto load_tile = [&](int s, int k0) {
        if (MODE == 0) {
            int m = tid >> 1, half = tid & 1;
            int gm = bm + m;
            bool ok = gm < M;
            const unsigned* arow = A + (size_t)gm * lda + k0;
            #pragma unroll
            for (int i = 0; i < 2; i++) {
                int kof = half * 16 + i * 8;
                cpa16(&ASD(s, m, kof),     ok ? (arow + kof)     : A, ok);
                cpa16(&ASD(s, m, kof + 4), ok ? (arow + kof + 4) : A, ok);
            }
        } else {
            #pragma unroll
            for (int j = 0; j < 16; j++) {
                int l = tid * 16 + j;
                int m = l >> 5, kk = l & 31;
                int gm = bm + m, gk2 = k0 + kk;
                size_t idx = 0; bool ok = false;
                if (MODE == 1) {
                    int b = gm >> 12, ss = gm & 4095;
                    int od = ss >> 8, oh = (ss >> 4) & 15, ow = ss & 15;
                    int r = gk2 >> 7, cc2 = gk2 & 127;
                    int kd = r >> 4, kh = (r >> 2) & 3, kw = r & 3;
                    int id = od * 2 - 1 + kd, ih = oh * 2 - 1 + kh, iw = ow * 2 - 1 + kw;
                    ok = (unsigned)id <= 31u && (unsigned)ih <= 31u && (unsigned)iw <= 31u;
                    idx = ((size_t)((b << 15) + (id << 10) + (ih << 5) + iw)) * 128 + cc2;
                } else {
                    int b = gm >> 12, ss = gm & 4095;
                    int od = ss >> 8, oh = (ss >> 4) & 15, ow = ss & 15;
                    int r = gk2 >> 8, cc2 = gk2 & 255;
                    int kd = r / 9; int r2 = r - kd * 9;
                    int kh = r2 / 3; int kw = r2 - kh * 3;
                    int id = od - 1 + kd, ih = oh - 1 + kh, iw = ow - 1 + kw;
                    ok = (unsigned)id <= 15u && (unsigned)ih <= 15u && (unsigned)iw <= 15u;
                    idx = ((size_t)((b << 12) + (id << 8) + (ih << 4) + iw)) * 256 + cc2;
                }
                cpa4(&ASD(s, m, kk), ok ? (A + idx) : A, ok);
            }
        }
        {
            // B tile 32 x 64 words: 512 x 16B chunks, 2 per thread
            int kk = tid >> 3, quad = tid & 7;
            const unsigned* brow = Bm + (size_t)(k0 + kk) * N + bn;
            #pragma unroll
            for (int i = 0; i < 2; i++) {
                int n = quad * 8 + i * 4;
                bool ok = (bn + n) < N;
                cpa16(&BSD(s, kk, n), ok ? (brow + n) : Bm, ok);
            }
        }
        asm volatile("cp.async.commit_group;\n");
    };

    load_tile(0, 0);
    for (int t = 0; t < ntiles; t++) {
        int s = t & 1;
        if (t + 1 < ntiles) {
            load_tile(s ^ 1, (t + 1) << 5);
            asm volatile("cp.async.wait_group 1;\n");
        } else {
            asm volatile("cp.async.wait_group 0;\n");
        }
        __syncthreads();
        #pragma unroll
        for (int ks = 0; ks < 4; ks++) {
            int kb2 = ks * 8;
            unsigned a[2][4];
            #pragma unroll
            for (int mt = 0; mt < 2; mt++) {
                int m0 = wm * 32 + mt * 16;
                a[mt][0] = ASD(s, m0 + g,     kb2 + t4);
                a[mt][1] = ASD(s, m0 + g + 8, kb2 + t4);
                a[mt][2] = ASD(s, m0 + g,     kb2 + t4 + 4);
                a[mt][3] = ASD(s, m0 + g + 8, kb2 + t4 + 4);
            }
            #pragma unroll
            for (int nt = 0; nt < 4; nt++) {
                int n0 = wn * 32 + nt * 8;
                unsigned b0 = BSD(s, kb2 + t4,     n0 + g);
                unsigned b1 = BSD(s, kb2 + t4 + 4, n0 + g);
                #pragma unroll
                for (int mt = 0; mt < 2; mt++) {
                    asm volatile(
                        "mma.sync.aligned.m16n8k16.row.col.f32.f16.f16.f32 "
                        "{%0,%1,%2,%3}, {%4,%5,%6,%7}, {%8,%9}, {%0,%1,%2,%3};"
                        : "+f"(c[mt][nt][0]), "+f"(c[mt][nt][1]),
                          "+f"(c[mt][nt][2]), "+f"(c[mt][nt][3])
                        : "r"(a[mt][0]), "r"(a[mt][1]), "r"(a[mt][2]), "r"(a[mt][3]),
                          "r"(b0), "r"(b1));
                }
            }
        }
        __syncthreads();
    }
    #pragma unroll
    for (int mt = 0; mt < 2; mt++) {
        #pragma unroll
        for (int nt = 0; nt < 4; nt++) {
            int gn0 = bn + wn * 32 + nt * 8 + 2 * t4;
            #pragma unroll
            for (int r = 0; r < 4; r++) {
                int gm = bm + wm * 32 + mt * 16 + g + (r >> 1) * 8;
                int gn = gn0 + (r & 1);
                if (gm < M && gn < N) {
                    float v = c[mt][nt][r];
                    if (bias) v += bias[gn];
                    if (do_relu) v = fmaxf(v, 0.f);
                    C[(size_t)gm * N + gn] = v;
                }
            }
        }
    }
}

// ------------------------- per-node scatter: kqvs1 = voxout[vox] + pos*Wpos + bias ---------
__global__ void knode_kernel(const float* __restrict__ pos) {
    int r = blockIdx.x;
    int b = r / NNODES, n = r - b * NNODES;
    float p0 = pos[n * 3], p1 = pos[n * 3 + 1], p2 = pos[n * 3 + 2];
    int i0 = (int)(p0 * 16.f - 1.f);
    int i1 = (int)(p1 * 16.f - 1.f);
    int i2 = (int)(p2 * 16.f - 1.f);
    int vox = (i0 << 8) + (i1 << 4) + i2;
    const float4* vrow = (const float4*)(g_voxout + ((size_t)((b << 12) + vox)) * 1024);
    const float4* wr0  = (const float4*)(g_wpos1);
    const float4* wr1  = (const float4*)(g_wpos1 + 1024);
    const float4* wr2  = (const float4*)(g_wpos1 + 2048);
    const float4* br   = (const float4*)(g_bias1);
    float4* drow = (float4*)(g_kqvs1 + (size_t)r * 1024);
    int c = threadIdx.x;
    float4 v = vrow[c], w0 = wr0[c], w1 = wr1[c], w2 = wr2[c], bb = br[c];
    float4 o;
    o.x = v.x + p0 * w0.x + p1 * w1.x + p2 * w2.x + bb.x;
    o.y = v.y + p0 * w0.y + p1 * w1.y + p2 * w2.y + bb.y;
    o.z = v.z + p0 * w0.z + p1 * w1.z + p2 * w2.z + bb.z;
    o.w = v.w + p0 * w0.w + p1 * w1.w + p2 * w2.w + bb.w;
    drow[c] = o;
}

// --------------- CSR gated aggregation + relu + fp16x2 pack (F/2 threads) ---------------
template<int F>
__global__ void agg_kernel(const float* __restrict__ base, unsigned* __restrict__ packed) {
    int node = blockIdx.x;
    int t = threadIdx.x;                 // 0 .. F/2-1
    int c0 = t * 2;
    const int stride = 4 * F;
    const float* nrow = base + (size_t)node * stride;
    float2 kv  = *(const float2*)(nrow + c0);
    float2 acc = *(const float2*)(nrow + 3 * F + c0);
    int s0 = __ldg(&g_off[node]), s1 = __ldg(&g_off[node + 1]);
    int i = s0;
    for (; i + 1 < s1; i += 2) {
        int srcA = __ldg(&g_srcs[i]);
        int srcB = __ldg(&g_srcs[i + 1]);
        const float* rA = base + (size_t)srcA * stride;
        const float* rB = base + (size_t)srcB * stride;
        float2 qA = *(const float2*)(rA + F + c0), vA = *(const float2*)(rA + 2 * F + c0);
        float2 qB = *(const float2*)(rB + F + c0), vB = *(const float2*)(rB + 2 * F + c0);
        acc.x += vA.x * (1.f / (1.f + __expf(-(kv.x + qA.x))));
        acc.y += vA.y * (1.f / (1.f + __expf(-(kv.y + qA.y))));
        acc.x += vB.x * (1.f / (1.f + __expf(-(kv.x + qB.x))));
        acc.y += vB.y * (1.f / (1.f + __expf(-(kv.y + qB.y))));
    }
    if (i < s1) {
        int src = __ldg(&g_srcs[i]);
        const float* rr = base + (size_t)src * stride;
        float2 q = *(const float2*)(rr + F + c0), v = *(const float2*)(rr + 2 * F + c0);
        acc.x += v.x * (1.f / (1.f + __expf(-(kv.x + q.x))));
        acc.y += v.y * (1.f / (1.f + __expf(-(kv.y + q.y))));
    }
    packed[(size_t)node * (F / 2) + t] = pack2(fmaxf(acc.x, 0.f), fmaxf(acc.y, 0.f));
}

// ------------------------- final tiny layer (N=3) -------------------------
__global__ void mlp2_kernel(const float* __restrict__ w, const float* __restrict__ bb,
                            float* __restrict__ out) {
    int r = blockIdx.x * blockDim.x + threadIdx.x;
    if (r >= NTOT) return;
    const float* row = g_h3 + (size_t)r * 64;
    float a0 = bb[0], a1 = bb[1], a2 = bb[2];
    #pragma unroll
    for (int k = 0; k < 64; k++) {
        float xv = row[k];
        a0 = fmaf(xv, __ldg(&w[k * 3 + 0]), a0);
        a1 = fmaf(xv, __ldg(&w[k * 3 + 1]), a1);
        a2 = fmaf(xv, __ldg(&w[k * 3 + 2]), a2);
    }
    out[r * 3 + 0] = fmaxf(a0, 0.f);
    out[r * 3 + 1] = fmaxf(a1, 0.f);
    out[r * 3 + 2] = fmaxf(a2, 0.f);
}

// ------------------------- launcher -------------------------
extern "C" void kernel_launch(void* const* d_in, const int* in_sizes, int n_in,
                              void* d_out, int out_size) {
    const float* x   = (const float*)d_in[0];
    const float* pos = (const float*)d_in[1];
    const float* w0  = (const float*)d_in[2];
    const float* g0  = (const float*)d_in[3];
    const float* b0  = (const float*)d_in[4];
    const float* w1  = (const float*)d_in[5];
    const float* g1  = (const float*)d_in[6];
    const float* b1  = (const float*)d_in[7];
    const float* w2  = (const float*)d_in[8];
    const float* g2  = (const float*)d_in[9];
    const float* b2  = (const float*)d_in[10];
    const float* gk1 = (const float*)d_in[11];
    const float* gq1 = (const float*)d_in[12];
    const float* gv1 = (const float*)d_in[13];
    const float* gs1 = (const float*)d_in[14];
    const float* gb1 = (const float*)d_in[15];
    const float* gk2 = (const float*)d_in[16];
    const float* gq2 = (const float*)d_in[17];
    const float* gv2 = (const float*)d_in[18];
    const float* gs2 = (const float*)d_in[19];
    const float* gb2 = (const float*)d_in[20];
    const float* m1w = (const float*)d_in[21];
    const float* m1b = (const float*)d_in[22];
    const float* m2w = (const float*)d_in[23];
    const float* m2b = (const float*)d_in[24];
    const int*   ei  = (const int*)d_in[25];
    float* out = (float*)d_out;

    float    *p_f1, *p_f2, *p_wpos1, *p_bias1, *p_bias2;
    float    *p_voxout, *p_kqvs1, *p_kqvs2, *p_h3;
    unsigned *p_f0h, *p_f1h, *p_f2h, *p_w1p, *p_w2p, *p_wfeat1p, *p_wcat2p, *p_m1wp;
    unsigned *p_h1h, *p_h2h;
    cudaGetSymbolAddress((void**)&p_f0h,     g_f0h);
    cudaGetSymbolAddress((void**)&p_f1,      g_f1);
    cudaGetSymbolAddress((void**)&p_f1h,     g_f1h);
    cudaGetSymbolAddress((void**)&p_f2,      g_f2);
    cudaGetSymbolAddress((void**)&p_f2h,     g_f2h);
    cudaGetSymbolAddress((void**)&p_w1p,     g_w1p);
    cudaGetSymbolAddress((void**)&p_w2p,     g_w2p);
    cudaGetSymbolAddress((void**)&p_wfeat1p, g_wfeat1p);
    cudaGetSymbolAddress((void**)&p_wpos1,   g_wpos1);
    cudaGetSymbolAddress((void**)&p_bias1,   g_bias1);
    cudaGetSymbolAddress((void**)&p_wcat2p,  g_wcat2p);
    cudaGetSymbolAddress((void**)&p_bias2,   g_bias2);
    cudaGetSymbolAddress((void**)&p_m1wp,    g_m1wp);
    cudaGetSymbolAddress((void**)&p_voxout,  g_voxout);
    cudaGetSymbolAddress((void**)&p_kqvs1,   g_kqvs1);
    cudaGetSymbolAddress((void**)&p_h1h,     g_h1h);
    cudaGetSymbolAddress((void**)&p_kqvs2,   g_kqvs2);
    cudaGetSymbolAddress((void**)&p_h2h,     g_h2h);
    cudaGetSymbolAddress((void**)&p_h3,      g_h3);

    cudaFuncSetAttribute(mma_gemm<0>, cudaFuncAttributeMaxDynamicSharedMemorySize, SMEM_BYTES);
    cudaFuncSetAttribute(mma_gemm<1>, cudaFuncAttributeMaxDynamicSharedMemorySize, SMEM_BYTES);
    cudaFuncSetAttribute(mma_gemm<2>, cudaFuncAttributeMaxDynamicSharedMemorySize, SMEM_BYTES);

    // -------- launches 1..4: keep the big conv1 GEMM at slot 4 (profiler samples it) ----
    pack_w1<<<CDIV(8192 * 512, 256), 256>>>(w1);                                        // 1
    conv0_kernel<<<dim3(128, 256, 2), 256>>>(x, w0);                                    // 2
    bn0_tr_kernel<<<dim3(1024, 8, 2), dim3(32, 8)>>>(g0, b0);                           // 3
    mma_gemm<1><<<dim3(8, 64), 256, SMEM_BYTES>>>(p_f0h, p_w1p, p_f1,                   // 4
                                                  8192, 512, 8192, 0, nullptr, 0);

    // reset conv0 stat accumulators (before conv1 stats accumulate)
    reset_cs<<<2, 256>>>();

    // conv1 bn -> fp16
    bn_stats_fast<<<256, 128>>>(p_f1, 8192);
    bn_final_rc<<<2, 256>>>(g1, b1, 1.f / 8192.f);
    bn_apply_rc_h<<<CDIV(1048576, 256), 256>>>(p_f1, p_f1h, 512, 1048576, 1);

    // conv2 + bn -> fp16
    pack_w2<<<CDIV(6912 * 512, 256), 256>>>(w2);
    mma_gemm<2><<<dim3(8, 64), 256, SMEM_BYTES>>>(p_f1h, p_w2p, p_f2, 8192, 512, 6912, 0, nullptr, 0);
    bn_stats_fast<<<256, 128>>>(p_f2, 8192);
    bn_final_rc<<<2, 256>>>(g2, b2, 1.f / 8192.f);
    bn_apply_rc_h<<<CDIV(1048576, 256), 256>>>(p_f2, p_f2h, 512, 1048576, 0);

    // CSR build
    hist_kernel<<<CDIV(NE2, 256), 256>>>(ei);
    scan1_kernel<<<SCAN_B, 1024>>>();
    scan2_kernel<<<1, 32>>>();
    scan3_kernel<<<SCAN_B, 1024>>>();
    fill_kernel<<<CDIV(NE2, 256), 256>>>(ei);

    // GNN weight prep (fp16x2 packed)
    pack_cols<<<CDIV(256 * 256, 256), 256>>>(gk1, p_wfeat1p, 3, 256, 256, 0,    1024);
    pack_cols<<<CDIV(256 * 256, 256), 256>>>(gq1, p_wfeat1p, 3, 256, 256, 256,  1024);
    pack_cols<<<CDIV(256 * 256, 256), 256>>>(gv1, p_wfeat1p, 3, 256, 256, 512,  1024);
    pack_cols<<<CDIV(256 * 256, 256), 256>>>(gs1, p_wfeat1p, 3, 256, 256, 768,  1024);
    copy_rows<<<3, 256>>>(gk1, p_wpos1, 3, 256, 0,   1024);
    copy_rows<<<3, 256>>>(gq1, p_wpos1, 3, 256, 256, 1024);
    copy_rows<<<3, 256>>>(gv1, p_wpos1, 3, 256, 512, 1024);
    copy_rows<<<3, 256>>>(gs1, p_wpos1, 3, 256, 768, 1024);
    pack_cols<<<CDIV(128 * 128, 256), 256>>>(gk2, p_wcat2p, 0, 128, 128, 0,   512);
    pack_cols<<<CDIV(128 * 128, 256), 256>>>(gq2, p_wcat2p, 0, 128, 128, 128, 512);
    pack_cols<<<CDIV(128 * 128, 256), 256>>>(gv2, p_wcat2p, 0, 128, 128, 256, 512);
    pack_cols<<<CDIV(128 * 128, 256), 256>>>(gs2, p_wcat2p, 0, 128, 128, 384, 512);
    pack_cols<<<CDIV(64 * 64, 256), 256>>>(m1w, p_m1wp, 0, 64, 64, 0, 64);
    build_bias<<<4, 256>>>(gb1, p_bias1, 768, 256, 1024);
    build_bias<<<2, 256>>>(gb2, p_bias2, 384, 128, 512);

    // voxel-level GNN1 GEMM: (8192, K2=256) @ (256, 1024)
    mma_gemm<0><<<dim3(16, 64), 256, SMEM_BYTES>>>(p_f2h, p_wfeat1p, p_voxout,
                                                   8192, 1024, 256, 256, nullptr, 0);
    knode_kernel<<<NTOT, 256>>>(pos);

    // GNN layer 1: CSR aggregation + relu + pack fp16
    agg_kernel<256><<<NTOT, 128>>>(p_kqvs1, p_h1h);

    // GNN layer 2: (100000, K2=128) @ (128, 512)
    mma_gemm<0><<<dim3(8, CDIV(NTOT, 128)), 256, SMEM_BYTES>>>(p_h1h, p_wcat2p, p_kqvs2,
                                                               NTOT, 512, 128, 128, p_bias2, 0);
    agg_kernel<128><<<NTOT, 64>>>(p_kqvs2, p_h2h);

    // MLP head: (100000, K2=64) @ (64, 64)
    mma_gemm<0><<<dim3(1, CDIV(NTOT, 128)), 256, SMEM_BYTES>>>(p_h2h, p_m1wp, p_h3,
                                                               NTOT, 64, 64, 64, m1b, 1);
    mlp2_kernel<<<CDIV(NTOT, 256), 256>>>(m2w, m2b, out);
}

// round 16
// speedup vs baseline: 1.3342x; 1.3342x over previous
#include <cuda_runtime.h>
#include <cuda_fp16.h>
#include <math.h>

#define CDIV(a,b) (((a)+(b)-1)/(b))

namespace {
constexpr int NNODES = 50000;
constexpr int NEDGES = 300000;
constexpr int NTOT   = 100000;
constexpr int NE2    = 2 * NEDGES;      // 600000
constexpr int SCAN_B = 98;              // CDIV(NTOT, 1024)
constexpr int SMEM_BYTES = (2 * 128 * 36 + 2 * 32 * 136) * 4;   // 71680
}

// ------------------------- static device scratch (zero-initialized at load) ----------
__device__ float    g_f0 [16777216];   // (2,256,32^3) conv0 out fp32
__device__ unsigned g_f0h[8388608];    // (2,32^3,128u) fp16x2 after bn+relu, (b,s,c)
__device__ float    g_f1 [4194304];    // (2,16^3,512) conv1 out fp32
__device__ unsigned g_f1h[2097152];    // (2,16^3,256u) fp16x2
__device__ float    g_f2 [4194304];    // conv2 out fp32
__device__ unsigned g_f2h[2097152];    // fp16x2
__device__ unsigned g_w1p[4194304];    // w1 packed (K2=8192, 512) fp16x2
__device__ unsigned g_w2p[3538944];    // w2 packed (K2=6912, 512) fp16x2
__device__ unsigned g_wfeat1p[262144]; // (K2=256, 1024) fp16x2
__device__ float    g_wpos1[3072];     // (3,1024) fp32 pos rows
__device__ float    g_bias1[1024];
__device__ unsigned g_wcat2p[65536];   // (K2=128, 512) fp16x2
__device__ float    g_bias2[512];
__device__ unsigned g_m1wp[4096];      // (K2=64, 64) fp16x2
__device__ float    g_voxout[8388608]; // (8192,1024) fp32
__device__ unsigned g_kqvs1h[51200000];// (100000, 512 words) fp16x2: [k|q|v|h] x 128 words
__device__ unsigned g_h1h[12800000];   // (100000,128u) fp16x2
__device__ unsigned g_kqvs2h[25600000];// (100000, 256 words) fp16x2
__device__ unsigned g_h2h[6400000];    // (100000,64u) fp16x2
__device__ float    g_h3[6400000];     // (100000,64)
__device__ float    g_scale[512];
__device__ float    g_shift[512];
// BN stat accumulators. INVARIANT: zero at entry of every kernel_launch call.
__device__ float    g_cs [512];
__device__ float    g_cs2[512];
// CSR. INVARIANT: g_deg zero at entry (self-cleaned by scan1).
__device__ int      g_deg[100352];
__device__ int      g_scan[100352];
__device__ int      g_bsum[SCAN_B];
__device__ int      g_off[100001];
__device__ int      g_cur[100000];
__device__ int      g_srcs[600000];

__device__ __forceinline__ unsigned pack2(float a, float b) {
    __half2 h = __floats2half2_rn(a, b);
    return *reinterpret_cast<unsigned*>(&h);
}
__device__ __forceinline__ float2 unpack2(unsigned u) {
    __half2 h = *reinterpret_cast<__half2*>(&u);
    return __half22float2(h);
}

__device__ __forceinline__ void cpa16(void* dst, const void* src, bool pred) {
    unsigned d = (unsigned)__cvta_generic_to_shared(dst);
    int sz = pred ? 16 : 0;
    asm volatile("cp.async.cg.shared.global [%0], [%1], 16, %2;\n" :: "r"(d), "l"(src), "r"(sz));
}
__device__ __forceinline__ void cpa4(void* dst, const void* src, bool pred) {
    unsigned d = (unsigned)__cvta_generic_to_shared(dst);
    int sz = pred ? 4 : 0;
    asm volatile("cp.async.ca.shared.global [%0], [%1], 4, %2;\n" :: "r"(d), "l"(src), "r"(sz));
}

// ------------------------- conv0: direct 3x3x3, C_in=4 + fused BN stats --------------
__global__ void conv0_kernel(const float* __restrict__ x, const float* __restrict__ w0) {
    __shared__ float ws[108];
    __shared__ float r1[256], r2[256];
    int co = blockIdx.y, b = blockIdx.z;
    if (threadIdx.x < 108) ws[threadIdx.x] = w0[co * 108 + threadIdx.x];
    __syncthreads();
    int s = blockIdx.x * 256 + threadIdx.x;
    int z = s >> 10, y = (s >> 5) & 31, xx = s & 31;
    float acc = 0.f;
    #pragma unroll
    for (int ci = 0; ci < 4; ci++) {
        const float* xb = x + ((size_t)(b * 4 + ci) << 15);
        const float* wc = ws + ci * 27;
        #pragma unroll
        for (int kd = 0; kd < 3; kd++) {
            int id = z + kd - 1;
            if ((unsigned)id > 31u) continue;
            #pragma unroll
            for (int kh = 0; kh < 3; kh++) {
                int ih = y + kh - 1;
                if ((unsigned)ih > 31u) continue;
                #pragma unroll
                for (int kw = 0; kw < 3; kw++) {
                    int iw = xx + kw - 1;
                    if ((unsigned)iw > 31u) continue;
                    acc = fmaf(xb[(id << 10) + (ih << 5) + iw], wc[kd * 9 + kh * 3 + kw], acc);
                }
            }
        }
    }
    g_f0[(((size_t)((b << 8) + co)) << 15) + s] = acc;
    int tid = threadIdx.x;
    r1[tid] = acc; r2[tid] = acc * acc; __syncthreads();
    for (int o = 128; o; o >>= 1) {
        if (tid < o) { r1[tid] += r1[tid + o]; r2[tid] += r2[tid + o]; }
        __syncthreads();
    }
    if (tid == 0) {
        atomicAdd(&g_cs[co],  r1[0]);
        atomicAdd(&g_cs2[co], r2[0]);
    }
}

// bn+relu+transpose: f0 (b,c,s) fp32 -> f0h (b,s,c/2) fp16x2
__global__ void bn0_tr_kernel(const float* __restrict__ gm, const float* __restrict__ bt) {
    __shared__ float tile[32][33];
    __shared__ float scw[32], shw[32];
    int b = blockIdx.z, c0 = blockIdx.y * 32, s0 = blockIdx.x * 32;
    int x = threadIdx.x, y = threadIdx.y;      // 32 x 8
    if (y == 0) {
        int c = c0 + x;
        float inv = 1.f / 65536.f;
        float mean = g_cs[c] * inv;
        float var  = g_cs2[c] * inv - mean * mean;
        float sc = gm[c] * rsqrtf(var + 1e-5f);
        scw[x] = sc; shw[x] = bt[c] - mean * sc;
    }
    __syncthreads();
    for (int i = y; i < 32; i += 8) {
        float v = g_f0[(((size_t)((b << 8) + c0 + i)) << 15) + s0 + x];
        tile[i][x] = fmaxf(v * scw[i] + shw[i], 0.f);
    }
    __syncthreads();
    if (x < 16) {
        for (int i = y; i < 32; i += 8) {
            int s = s0 + i;
            g_f0h[((size_t)(b << 15) + s) * 128 + (c0 >> 1) + x] =
                pack2(tile[2 * x][i], tile[2 * x + 1][i]);
        }
    }
}

__global__ void reset_cs() {
    int c = threadIdx.x + blockIdx.x * 256;   // 512
    g_cs[c] = 0.f; g_cs2[c] = 0.f;
}

// ------------------------- fast BN stats, layout (rows, 512) -------------------------
__global__ void bn_stats_fast(const float* __restrict__ x, int rows) {
    int tid = threadIdx.x;               // 0..127
    int rpb = rows / gridDim.x;
    int r0 = blockIdx.x * rpb;
    float a1x = 0.f, a1y = 0.f, a1z = 0.f, a1w = 0.f;
    float a2x = 0.f, a2y = 0.f, a2z = 0.f, a2w = 0.f;
    const float4* xr = (const float4*)x;
    for (int r = r0; r < r0 + rpb; r++) {
        float4 v = xr[(size_t)r * 128 + tid];
        a1x += v.x; a1y += v.y; a1z += v.z; a1w += v.w;
        a2x += v.x * v.x; a2y += v.y * v.y; a2z += v.z * v.z; a2w += v.w * v.w;
    }
    int c = tid * 4;
    atomicAdd(&g_cs[c + 0], a1x); atomicAdd(&g_cs2[c + 0], a2x);
    atomicAdd(&g_cs[c + 1], a1y); atomicAdd(&g_cs2[c + 1], a2y);
    atomicAdd(&g_cs[c + 2], a1z); atomicAdd(&g_cs2[c + 2], a2z);
    atomicAdd(&g_cs[c + 3], a1w); atomicAdd(&g_cs2[c + 3], a2w);
}

__global__ void bn_final_rc(const float* __restrict__ gm, const float* __restrict__ bt,
                            float invRows) {
    int c = blockIdx.x * 256 + threadIdx.x;   // 512
    float mean = g_cs[c] * invRows;
    float var  = g_cs2[c] * invRows - mean * mean;
    float sc = gm[c] * rsqrtf(var + 1e-5f);
    g_scale[c] = sc;
    g_shift[c] = bt[c] - mean * sc;
    g_cs[c] = 0.f; g_cs2[c] = 0.f;            // self-clean for next use
}

// bn-apply -> fp16x2, layout (rows, C) float4 in, uint2 out
__global__ void bn_apply_rc_h(const float* __restrict__ x, unsigned* __restrict__ o,
                              int C, int n4, int do_relu) {
    int i = blockIdx.x * blockDim.x + threadIdx.x;
    if (i >= n4) return;
    int c = (i * 4) % C;
    float4 v = ((const float4*)x)[i];
    v.x = v.x * g_scale[c]     + g_shift[c];
    v.y = v.y * g_scale[c + 1] + g_shift[c + 1];
    v.z = v.z * g_scale[c + 2] + g_shift[c + 2];
    v.w = v.w * g_scale[c + 3] + g_shift[c + 3];
    if (do_relu) {
        v.x = fmaxf(v.x, 0.f); v.y = fmaxf(v.y, 0.f);
        v.z = fmaxf(v.z, 0.f); v.w = fmaxf(v.w, 0.f);
    }
    uint2 u; u.x = pack2(v.x, v.y); u.y = pack2(v.z, v.w);
    ((uint2*)o)[i] = u;
}

// ------------------------- weight prep (fp16x2 packed along K) -------------------------
__global__ void pack_w1(const float* __restrict__ w1) {
    int i = blockIdx.x * blockDim.x + threadIdx.x;   // k2 * 512 + co, k2 < 8192
    if (i >= 8192 * 512) return;
    int k2 = i >> 9, co = i & 511;
    int r = k2 >> 7, ci = (k2 & 127) * 2;
    size_t base = (size_t)co * 16384 + (size_t)ci * 64 + r;
    g_w1p[i] = pack2(w1[base], w1[base + 64]);
}

__global__ void pack_w2(const float* __restrict__ w2) {
    int i = blockIdx.x * blockDim.x + threadIdx.x;   // k2 * 512 + co, k2 < 6912
    if (i >= 6912 * 512) return;
    int k2 = i >> 9, co = i & 511;
    int r = k2 >> 8, ci = (k2 & 255) * 2;
    size_t base = (size_t)co * 13824 + (size_t)ci * 27 + r;
    g_w2p[i] = pack2(w2[base], w2[base + 27]);
}

__global__ void pack_cols(const float* __restrict__ src, unsigned* __restrict__ dst,
                          int rowOff, int K2, int F, int off, int Nout) {
    int i = blockIdx.x * blockDim.x + threadIdx.x;
    if (i >= K2 * F) return;
    int k2 = i / F, f = i - k2 * F;
    float a = src[(size_t)(2 * k2 + rowOff) * F + f];
    float b = src[(size_t)(2 * k2 + 1 + rowOff) * F + f];
    dst[(size_t)k2 * Nout + off + f] = pack2(a, b);
}

__global__ void copy_rows(const float* __restrict__ src, float* __restrict__ dst,
                          int rows, int F, int off, int Nout) {
    int i = blockIdx.x * blockDim.x + threadIdx.x;
    if (i >= rows * F) return;
    int k = i / F, f = i - k * F;
    dst[(size_t)k * Nout + off + f] = src[(size_t)k * F + f];
}

__global__ void build_bias(const float* __restrict__ src, float* __restrict__ dst,
                           int off, int F, int Nout) {
    int i = blockIdx.x * blockDim.x + threadIdx.x;
    if (i >= Nout) return;
    dst[i] = (i >= off && i < off + F) ? src[i - off] : 0.f;
}

// ------------------------- CSR build -------------------------
__global__ void hist_kernel(const int* __restrict__ ei) {
    int j = blockIdx.x * blockDim.x + threadIdx.x;
    if (j >= NE2) return;
    int b = (j >= NEDGES) ? 1 : 0;
    int e = j - b * NEDGES;
    int dst = __ldg(ei + NEDGES + e) + b * NNODES;
    atomicAdd(&g_deg[dst], 1);
}

__global__ void scan1_kernel() {
    __shared__ int tmp[1024];
    int tid = threadIdx.x;
    int gid = blockIdx.x * 1024 + tid;
    int v = (gid < NTOT) ? g_deg[gid] : 0;
    g_deg[gid] = 0;                      // self-clean
    tmp[tid] = v;
    __syncthreads();
    for (int o = 1; o < 1024; o <<= 1) {
        int t = (tid >= o) ? tmp[tid - o] : 0;
        __syncthreads();
        tmp[tid] += t;
        __syncthreads();
    }
    g_scan[gid] = tmp[tid] - v;
    if (tid == 1023) g_bsum[blockIdx.x] = tmp[1023];
}

__global__ void scan2_kernel() {
    if (threadIdx.x == 0) {
        int run = 0;
        for (int i = 0; i < SCAN_B; i++) { int t = g_bsum[i]; g_bsum[i] = run; run += t; }
        g_off[NTOT] = NE2;
    }
}

__global__ void scan3_kernel() {
    int gid = blockIdx.x * 1024 + threadIdx.x;
    if (gid >= NTOT) return;
    int o = g_scan[gid] + g_bsum[blockIdx.x];
    g_off[gid] = o;
    g_cur[gid] = o;
}

__global__ void fill_kernel(const int* __restrict__ ei) {
    int j = blockIdx.x * blockDim.x + threadIdx.x;
    if (j >= NE2) return;
    int b = (j >= NEDGES) ? 1 : 0;
    int e = j - b * NEDGES;
    int src = __ldg(ei + e) + b * NNODES;
    int dst = __ldg(ei + NEDGES + e) + b * NNODES;
    int pos = atomicAdd(&g_cur[dst], 1);
    g_srcs[pos] = src;
}

// -------- fp16 tensor-core GEMM (m16n8k16, 128x128 tile, cp.async 2-stage, 2 CTAs/SM) ----
// OUTH=0: fp32 C. OUTH=1: C is fp16x2-packed (N/2 words per row), bias added pre-pack.
#define ASD(s,m,k) sA[(s) * 4608 + (m) * 36 + (k)]
#define BSD(s,k,n) sB[(s) * 4352 + (k) * 136 + (n)]
template<int MODE, int OUTH>
__global__ void __launch_bounds__(256, 2)
mma_gemm(const unsigned* __restrict__ A, const unsigned* __restrict__ Bm,
         float* __restrict__ C, int M, int N, int K2, int lda,
         const float* __restrict__ bias, int do_relu) {
    extern __shared__ unsigned sm_raw[];
    unsigned* sA = sm_raw;            // 2 * 128 * 36
    unsigned* sB = sm_raw + 9216;     // 2 * 32 * 136
    int tid = threadIdx.x;
    int bm = blockIdx.y * 128, bn = blockIdx.x * 128;
    int warp = tid >> 5, lane = tid & 31;
    int wm = warp & 3, wn = warp >> 2;
    int g = lane >> 2, t4 = lane & 3;

    float c[2][8][4];
    #pragma unroll
    for (int i = 0; i < 2; i++)
        #pragma unroll
        for (int j = 0; j < 8; j++)
            #pragma unroll
            for (int r = 0; r < 4; r++) c[i][j][r] = 0.f;

    int ntiles = K2 >> 5;

    auto load_tile = [&](int s, int k0) {
        if (MODE == 0) {
            int m = tid >> 1, half = tid & 1;
            int gm = bm + m;
            bool ok = gm < M;
            const unsigned* arow = A + (size_t)gm * lda + k0;
            #pragma unroll
            for (int i = 0; i < 2; i++) {
                int kof = half * 16 + i * 8;
                cpa16(&ASD(s, m, kof),     ok ? (arow + kof)     : A, ok);
                cpa16(&ASD(s, m, kof + 4), ok ? (arow + kof + 4) : A, ok);
            }
        } else {
            #pragma unroll
            for (int j = 0; j < 16; j++) {
                int l = tid * 16 + j;
                int m = l >> 5, kk = l & 31;
                int gm = bm + m, gk2 = k0 + kk;
                size_t idx = 0; bool ok = false;
                if (MODE == 1) {
                    int b = gm >> 12, ss = gm & 4095;
                    int od = ss >> 8, oh = (ss >> 4) & 15, ow = ss & 15;
                    int r = gk2 >> 7, cc2 = gk2 & 127;
                    int kd = r >> 4, kh = (r >> 2) & 3, kw = r & 3;
                    int id = od * 2 - 1 + kd, ih = oh * 2 - 1 + kh, iw = ow * 2 - 1 + kw;
                    ok = (unsigned)id <= 31u && (unsigned)ih <= 31u && (unsigned)iw <= 31u;
                    idx = ((size_t)((b << 15) + (id << 10) + (ih << 5) + iw)) * 128 + cc2;
                } else {
                    int b = gm >> 12, ss = gm & 4095;
                    int od = ss >> 8, oh = (ss >> 4) & 15, ow = ss & 15;
                    int r = gk2 >> 8, cc2 = gk2 & 255;
                    int kd = r / 9; int r2 = r - kd * 9;
                    int kh = r2 / 3; int kw = r2 - kh * 3;
                    int id = od - 1 + kd, ih = oh - 1 + kh, iw = ow - 1 + kw;
                    ok = (unsigned)id <= 15u && (unsigned)ih <= 15u && (unsigned)iw <= 15u;
                    idx = ((size_t)((b << 12) + (id << 8) + (ih << 4) + iw)) * 256 + cc2;
                }
                cpa4(&ASD(s, m, kk), ok ? (A + idx) : A, ok);
            }
        }
        {
            int kk = tid >> 3, quad = tid & 7;
            const unsigned* brow = Bm + (size_t)(k0 + kk) * N + bn;
            #pragma unroll
            for (int i = 0; i < 4; i++) {
                int n = quad * 16 + i * 4;
                bool ok = (bn + n) < N;
                cpa16(&BSD(s, kk, n), ok ? (brow + n) : Bm, ok);
            }
        }
        asm volatile("cp.async.commit_group;\n");
    };

    load_tile(0, 0);
    for (int t = 0; t < ntiles; t++) {
        int s = t & 1;
        if (t + 1 < ntiles) {
            load_tile(s ^ 1, (t + 1) << 5);
            asm volatile("cp.async.wait_group 1;\n");
        } else {
            asm volatile("cp.async.wait_group 0;\n");
        }
        __syncthreads();
        #pragma unroll
        for (int ks = 0; ks < 4; ks++) {
            int kb2 = ks * 8;
            unsigned a[2][4];
            #pragma unroll
            for (int mt = 0; mt < 2; mt++) {
                int m0 = wm * 32 + mt * 16;
                a[mt][0] = ASD(s, m0 + g,     kb2 + t4);
                a[mt][1] = ASD(s, m0 + g + 8, kb2 + t4);
                a[mt][2] = ASD(s, m0 + g,     kb2 + t4 + 4);
                a[mt][3] = ASD(s, m0 + g + 8, kb2 + t4 + 4);
            }
            #pragma unroll
            for (int nt = 0; nt < 8; nt++) {
                int n0 = wn * 64 + nt * 8;
                unsigned b0 = BSD(s, kb2 + t4,     n0 + g);
                unsigned b1 = BSD(s, kb2 + t4 + 4, n0 + g);
                #pragma unroll
                for (int mt = 0; mt < 2; mt++) {
                    asm volatile(
                        "mma.sync.aligned.m16n8k16.row.col.f32.f16.f16.f32 "
                        "{%0,%1,%2,%3}, {%4,%5,%6,%7}, {%8,%9}, {%0,%1,%2,%3};"
                        : "+f"(c[mt][nt][0]), "+f"(c[mt][nt][1]),
                          "+f"(c[mt][nt][2]), "+f"(c[mt][nt][3])
                        : "r"(a[mt][0]), "r"(a[mt][1]), "r"(a[mt][2]), "r"(a[mt][3]),
                          "r"(b0), "r"(b1));
                }
            }
        }
        __syncthreads();
    }
    #pragma unroll
    for (int mt = 0; mt < 2; mt++) {
        #pragma unroll
        for (int nt = 0; nt < 8; nt++) {
            int gn0 = bn + wn * 64 + nt * 8 + 2 * t4;
            if (OUTH) {
                #pragma unroll
                for (int h = 0; h < 2; h++) {
                    int gm = bm + wm * 32 + mt * 16 + g + h * 8;
                    if (gm < M) {
                        float v0 = c[mt][nt][h * 2 + 0];
                        float v1 = c[mt][nt][h * 2 + 1];
                        if (bias) { v0 += bias[gn0]; v1 += bias[gn0 + 1]; }
                        if (do_relu) { v0 = fmaxf(v0, 0.f); v1 = fmaxf(v1, 0.f); }
                        ((unsigned*)C)[(size_t)gm * (N >> 1) + (gn0 >> 1)] = pack2(v0, v1);
                    }
                }
            } else {
                #pragma unroll
                for (int r = 0; r < 4; r++) {
                    int gm = bm + wm * 32 + mt * 16 + g + (r >> 1) * 8;
                    int gn = gn0 + (r & 1);
                    if (gm < M && gn < N) {
                        float v = c[mt][nt][r];
                        if (bias) v += bias[gn];
                        if (do_relu) v = fmaxf(v, 0.f);
                        C[(size_t)gm * N + gn] = v;
                    }
                }
            }
        }
    }
}

// ---------- per-node scatter: kqvs1h = pack(voxout[vox] + pos*Wpos + bias) -------------
__global__ void knode_kernel(const float* __restrict__ pos) {
    int r = blockIdx.x;
    int b = r / NNODES, n = r - b * NNODES;
    float p0 = pos[n * 3], p1 = pos[n * 3 + 1], p2 = pos[n * 3 + 2];
    int i0 = (int)(p0 * 16.f - 1.f);
    int i1 = (int)(p1 * 16.f - 1.f);
    int i2 = (int)(p2 * 16.f - 1.f);
    int vox = (i0 << 8) + (i1 << 4) + i2;
    const float4* vrow = (const float4*)(g_voxout + ((size_t)((b << 12) + vox)) * 1024);
    const float4* wr0  = (const float4*)(g_wpos1);
    const float4* wr1  = (const float4*)(g_wpos1 + 1024);
    const float4* wr2  = (const float4*)(g_wpos1 + 2048);
    const float4* br   = (const float4*)(g_bias1);
    uint2* drow = (uint2*)(g_kqvs1h + (size_t)r * 512);
    int c = threadIdx.x;                 // 0..255, 4 channels each
    float4 v = vrow[c], w0 = wr0[c], w1 = wr1[c], w2 = wr2[c], bb = br[c];
    float4 o;
    o.x = v.x + p0 * w0.x + p1 * w1.x + p2 * w2.x + bb.x;
    o.y = v.y + p0 * w0.y + p1 * w1.y + p2 * w2.y + bb.y;
    o.z = v.z + p0 * w0.z + p1 * w1.z + p2 * w2.z + bb.z;
    o.w = v.w + p0 * w0.w + p1 * w1.w + p2 * w2.w + bb.w;
    uint2 u; u.x = pack2(o.x, o.y); u.y = pack2(o.z, o.w);
    drow[c] = u;
}

// --------- CSR gated aggregation on fp16x2 rows + relu + fp16x2 pack (F/2 threads) --------
// row layout: [k|q|v|h], each F halves = F/2 words, row stride 2F words.
template<int F>
__global__ void agg_kernel(const unsigned* __restrict__ base, unsigned* __restrict__ packed) {
    int node = blockIdx.x;
    int t = threadIdx.x;                 // 0 .. F/2-1
    const int strideW = 2 * F;
    const int seg = F / 2;
    const unsigned* nrow = base + (size_t)node * strideW;
    float2 kv  = unpack2(nrow[t]);
    float2 acc = unpack2(nrow[3 * seg + t]);
    int s0 = __ldg(&g_off[node]), s1 = __ldg(&g_off[node + 1]);
    int i = s0;
    for (; i + 1 < s1; i += 2) {
        int srcA = __ldg(&g_srcs[i]);
        int srcB = __ldg(&g_srcs[i + 1]);
        const unsigned* rA = base + (size_t)srcA * strideW;
        const unsigned* rB = base + (size_t)srcB * strideW;
        float2 qA = unpack2(rA[seg + t]), vA = unpack2(rA[2 * seg + t]);
        float2 qB = unpack2(rB[seg + t]), vB = unpack2(rB[2 * seg + t]);
        acc.x += vA.x * (1.f / (1.f + __expf(-(kv.x + qA.x))));
        acc.y += vA.y * (1.f / (1.f + __expf(-(kv.y + qA.y))));
        acc.x += vB.x * (1.f / (1.f + __expf(-(kv.x + qB.x))));
        acc.y += vB.y * (1.f / (1.f + __expf(-(kv.y + qB.y))));
    }
    if (i < s1) {
        int src = __ldg(&g_srcs[i]);
        const unsigned* rr = base + (size_t)src * strideW;
        float2 q = unpack2(rr[seg + t]), v = unpack2(rr[2 * seg + t]);
        acc.x += v.x * (1.f / (1.f + __expf(-(kv.x + q.x))));
        acc.y += v.y * (1.f / (1.f + __expf(-(kv.y + q.y))));
    }
    packed[(size_t)node * seg + t] = pack2(fmaxf(acc.x, 0.f), fmaxf(acc.y, 0.f));
}

// ------------------------- final tiny layer (N=3) -------------------------
__global__ void mlp2_kernel(const float* __restrict__ w, const float* __restrict__ bb,
                            float* __restrict__ out) {
    int r = blockIdx.x * blockDim.x + threadIdx.x;
    if (r >= NTOT) return;
    const float* row = g_h3 + (size_t)r * 64;
    float a0 = bb[0], a1 = bb[1], a2 = bb[2];
    #pragma unroll
    for (int k = 0; k < 64; k++) {
        float xv = row[k];
        a0 = fmaf(xv, __ldg(&w[k * 3 + 0]), a0);
        a1 = fmaf(xv, __ldg(&w[k * 3 + 1]), a1);
        a2 = fmaf(xv, __ldg(&w[k * 3 + 2]), a2);
    }
    out[r * 3 + 0] = fmaxf(a0, 0.f);
    out[r * 3 + 1] = fmaxf(a1, 0.f);
    out[r * 3 + 2] = fmaxf(a2, 0.f);
}

// ------------------------- launcher -------------------------
extern "C" void kernel_launch(void* const* d_in, const int* in_sizes, int n_in,
                              void* d_out, int out_size) {
    const float* x   = (const float*)d_in[0];
    const float* pos = (const float*)d_in[1];
    const float* w0  = (const float*)d_in[2];
    const float* g0  = (const float*)d_in[3];
    const float* b0  = (const float*)d_in[4];
    const float* w1  = (const float*)d_in[5];
    const float* g1  = (const float*)d_in[6];
    const float* b1  = (const float*)d_in[7];
    const float* w2  = (const float*)d_in[8];
    const float* g2  = (const float*)d_in[9];
    const float* b2  = (const float*)d_in[10];
    const float* gk1 = (const float*)d_in[11];
    const float* gq1 = (const float*)d_in[12];
    const float* gv1 = (const float*)d_in[13];
    const float* gs1 = (const float*)d_in[14];
    const float* gb1 = (const float*)d_in[15];
    const float* gk2 = (const float*)d_in[16];
    const float* gq2 = (const float*)d_in[17];
    const float* gv2 = (const float*)d_in[18];
    const float* gs2 = (const float*)d_in[19];
    const float* gb2 = (const float*)d_in[20];
    const float* m1w = (const float*)d_in[21];
    const float* m1b = (const float*)d_in[22];
    const float* m2w = (const float*)d_in[23];
    const float* m2b = (const float*)d_in[24];
    const int*   ei  = (const int*)d_in[25];
    float* out = (float*)d_out;

    float    *p_f1, *p_f2, *p_wpos1, *p_bias1, *p_bias2;
    float    *p_voxout, *p_h3;
    unsigned *p_f0h, *p_f1h, *p_f2h, *p_w1p, *p_w2p, *p_wfeat1p, *p_wcat2p, *p_m1wp;
    unsigned *p_kqvs1h, *p_kqvs2h, *p_h1h, *p_h2h;
    cudaGetSymbolAddress((void**)&p_f0h,     g_f0h);
    cudaGetSymbolAddress((void**)&p_f1,      g_f1);
    cudaGetSymbolAddress((void**)&p_f1h,     g_f1h);
    cudaGetSymbolAddress((void**)&p_f2,      g_f2);
    cudaGetSymbolAddress((void**)&p_f2h,     g_f2h);
    cudaGetSymbolAddress((void**)&p_w1p,     g_w1p);
    cudaGetSymbolAddress((void**)&p_w2p,     g_w2p);
    cudaGetSymbolAddress((void**)&p_wfeat1p, g_wfeat1p);
    cudaGetSymbolAddress((void**)&p_wpos1,   g_wpos1);
    cudaGetSymbolAddress((void**)&p_bias1,   g_bias1);
    cudaGetSymbolAddress((void**)&p_wcat2p,  g_wcat2p);
    cudaGetSymbolAddress((void**)&p_bias2,   g_bias2);
    cudaGetSymbolAddress((void**)&p_m1wp,    g_m1wp);
    cudaGetSymbolAddress((void**)&p_voxout,  g_voxout);
    cudaGetSymbolAddress((void**)&p_kqvs1h,  g_kqvs1h);
    cudaGetSymbolAddress((void**)&p_h1h,     g_h1h);
    cudaGetSymbolAddress((void**)&p_kqvs2h,  g_kqvs2h);
    cudaGetSymbolAddress((void**)&p_h2h,     g_h2h);
    cudaGetSymbolAddress((void**)&p_h3,      g_h3);

    cudaFuncSetAttribute(mma_gemm<0, 0>, cudaFuncAttributeMaxDynamicSharedMemorySize, SMEM_BYTES);
    cudaFuncSetAttribute(mma_gemm<0, 1>, cudaFuncAttributeMaxDynamicSharedMemorySize, SMEM_BYTES);
    cudaFuncSetAttribute(mma_gemm<1, 0>, cudaFuncAttributeMaxDynamicSharedMemorySize, SMEM_BYTES);
    cudaFuncSetAttribute(mma_gemm<2, 0>, cudaFuncAttributeMaxDynamicSharedMemorySize, SMEM_BYTES);

    // -------- launches 1..4: keep the big conv1 GEMM at slot 4 (profiler samples it) ----
    pack_w1<<<CDIV(8192 * 512, 256), 256>>>(w1);                                        // 1
    conv0_kernel<<<dim3(128, 256, 2), 256>>>(x, w0);                                    // 2
    bn0_tr_kernel<<<dim3(1024, 8, 2), dim3(32, 8)>>>(g0, b0);                           // 3
    mma_gemm<1, 0><<<dim3(4, 64), 256, SMEM_BYTES>>>(p_f0h, p_w1p, p_f1,                // 4
                                                     8192, 512, 8192, 0, nullptr, 0);

    // reset conv0 stat accumulators (before conv1 stats accumulate)
    reset_cs<<<2, 256>>>();

    // conv1 bn -> fp16
    bn_stats_fast<<<256, 128>>>(p_f1, 8192);
    bn_final_rc<<<2, 256>>>(g1, b1, 1.f / 8192.f);
    bn_apply_rc_h<<<CDIV(1048576, 256), 256>>>(p_f1, p_f1h, 512, 1048576, 1);

    // conv2 + bn -> fp16
    pack_w2<<<CDIV(6912 * 512, 256), 256>>>(w2);
    mma_gemm<2, 0><<<dim3(4, 64), 256, SMEM_BYTES>>>(p_f1h, p_w2p, p_f2, 8192, 512, 6912, 0, nullptr, 0);
    bn_stats_fast<<<256, 128>>>(p_f2, 8192);
    bn_final_rc<<<2, 256>>>(g2, b2, 1.f / 8192.f);
    bn_apply_rc_h<<<CDIV(1048576, 256), 256>>>(p_f2, p_f2h, 512, 1048576, 0);

    // CSR build
    hist_kernel<<<CDIV(NE2, 256), 256>>>(ei);
    scan1_kernel<<<SCAN_B, 1024>>>();
    scan2_kernel<<<1, 32>>>();
    scan3_kernel<<<SCAN_B, 1024>>>();
    fill_kernel<<<CDIV(NE2, 256), 256>>>(ei);

    // GNN weight prep (fp16x2 packed)
    pack_cols<<<CDIV(256 * 256, 256), 256>>>(gk1, p_wfeat1p, 3, 256, 256, 0,    1024);
    pack_cols<<<CDIV(256 * 256, 256), 256>>>(gq1, p_wfeat1p, 3, 256, 256, 256,  1024);
    pack_cols<<<CDIV(256 * 256, 256), 256>>>(gv1, p_wfeat1p, 3, 256, 256, 512,  1024);
    pack_cols<<<CDIV(256 * 256, 256), 256>>>(gs1, p_wfeat1p, 3, 256, 256, 768,  1024);
    copy_rows<<<3, 256>>>(gk1, p_wpos1, 3, 256, 0,   1024);
    copy_rows<<<3, 256>>>(gq1, p_wpos1, 3, 256, 256, 1024);
    copy_rows<<<3, 256>>>(gv1, p_wpos1, 3, 256, 512, 1024);
    copy_rows<<<3, 256>>>(gs1, p_wpos1, 3, 256, 768, 1024);
    pack_cols<<<CDIV(128 * 128, 256), 256>>>(gk2, p_wcat2p, 0, 128, 128, 0,   512);
    pack_cols<<<CDIV(128 * 128, 256), 256>>>(gq2, p_wcat2p, 0, 128, 128, 128, 512);
    pack_cols<<<CDIV(128 * 128, 256), 256>>>(gv2, p_wcat2p, 0, 128, 128, 256, 512);
    pack_cols<<<CDIV(128 * 128, 256), 256>>>(gs2, p_wcat2p, 0, 128, 128, 384, 512);
    pack_cols<<<CDIV(64 * 64, 256), 256>>>(m1w, p_m1wp, 0, 64, 64, 0, 64);
    build_bias<<<4, 256>>>(gb1, p_bias1, 768, 256, 1024);
    build_bias<<<2, 256>>>(gb2, p_bias2, 384, 128, 512);

    // voxel-level GNN1 GEMM: (8192, K2=256) @ (256, 1024) -> fp32 voxout
    mma_gemm<0, 0><<<dim3(8, 64), 256, SMEM_BYTES>>>(p_f2h, p_wfeat1p, p_voxout,
                                                     8192, 1024, 256, 256, nullptr, 0);
    knode_kernel<<<NTOT, 256>>>(pos);

    // GNN layer 1: CSR aggregation (fp16 rows) + relu + pack
    agg_kernel<256><<<NTOT, 128>>>(p_kqvs1h, p_h1h);

    // GNN layer 2: (100000, K2=128) @ (128, 512) -> fp16 packed kqvs2h (+bias2)
    mma_gemm<0, 1><<<dim3(4, CDIV(NTOT, 128)), 256, SMEM_BYTES>>>(
        p_h1h, p_wcat2p, (float*)p_kqvs2h, NTOT, 512, 128, 128, p_bias2, 0);
    agg_kernel<128><<<NTOT, 64>>>(p_kqvs2h, p_h2h);

    // MLP head: (100000, K2=64) @ (64, 64) -> fp32 h3
    mma_gemm<0, 0><<<dim3(1, CDIV(NTOT, 128)), 256, SMEM_BYTES>>>(p_h2h, p_m1wp, p_h3,
                                                                  NTOT, 64, 64, 64, m1b, 1);
    mlp2_kernel<<<CDIV(NTOT, 256), 256>>>(m2w, m2b, out);
}

// round 17
// speedup vs baseline: 1.5994x; 1.1987x over previous
#include <cuda_runtime.h>
#include <cuda_fp16.h>
#include <math.h>

#define CDIV(a,b) (((a)+(b)-1)/(b))

namespace {
constexpr int NNODES = 50000;
constexpr int NEDGES = 300000;
constexpr int NTOT   = 100000;
constexpr int NE2    = 2 * NEDGES;      // 600000
constexpr int SCAN_B = 98;              // CDIV(NTOT, 1024)
constexpr int SMEM_BYTES = (2 * 128 * 36 + 2 * 32 * 136) * 4;   // 71680
}

// ------------------------- static device scratch (zero-initialized at load) ----------
__device__ float    g_f0 [16777216];   // (2,256,32^3) conv0 out fp32
__device__ unsigned g_f0h[8388608];    // (2,32^3,128u) fp16x2 after bn+relu, (b,s,c)
__device__ float    g_f1 [4194304];    // (2,16^3,512) conv1 out fp32
__device__ unsigned g_f1h[2097152];    // (2,16^3,256u) fp16x2
__device__ float    g_f2 [4194304];    // conv2 out fp32
__device__ unsigned g_f2h[2097152];    // fp16x2
__device__ unsigned g_w1p[4194304];    // w1 packed (K2=8192, 512) fp16x2
__device__ unsigned g_w2p[3538944];    // w2 packed (K2=6912, 512) fp16x2
__device__ unsigned g_wfeat1p[262144]; // (K2=256, 1024) fp16x2
__device__ float    g_wpos1[3072];     // (3,1024) fp32 pos rows
__device__ float    g_bias1[1024];
__device__ unsigned g_wcat2p[65536];   // (K2=128, 512) fp16x2
__device__ float    g_bias2[512];
__device__ unsigned g_m1wp[4096];      // (K2=64, 64) fp16x2
__device__ float    g_voxout[8388608]; // (8192,1024) fp32
__device__ unsigned g_kqvs1h[51200000];// (100000, 512 words) fp16x2: [k|q|v|h] x 128 words
__device__ unsigned g_h1h[12800000];   // (100000,128u) fp16x2
__device__ unsigned g_kqvs2h[25600000];// (100000, 256 words) fp16x2
__device__ unsigned g_h2h[6400000];    // (100000,64u) fp16x2
__device__ float    g_h3[6400000];     // (100000,64)
__device__ float    g_scale[512];
__device__ float    g_shift[512];
// BN stat accumulators. INVARIANT: zero at entry of every kernel_launch call.
__device__ float    g_cs [512];
__device__ float    g_cs2[512];
// CSR. INVARIANT: g_deg zero at entry (self-cleaned by scan1).
__device__ int      g_deg[100352];
__device__ int      g_scan[100352];
__device__ int      g_bsum[SCAN_B];
__device__ int      g_off[100001];
__device__ int      g_cur[100000];
__device__ int      g_srcs[600000];

__device__ __forceinline__ unsigned pack2(float a, float b) {
    __half2 h = __floats2half2_rn(a, b);
    return *reinterpret_cast<unsigned*>(&h);
}
__device__ __forceinline__ float2 unpack2(unsigned u) {
    __half2 h = *reinterpret_cast<__half2*>(&u);
    return __half22float2(h);
}

__device__ __forceinline__ void cpa16(void* dst, const void* src, bool pred) {
    unsigned d = (unsigned)__cvta_generic_to_shared(dst);
    int sz = pred ? 16 : 0;
    asm volatile("cp.async.cg.shared.global [%0], [%1], 16, %2;\n" :: "r"(d), "l"(src), "r"(sz));
}

// ------------------------- conv0: direct 3x3x3, C_in=4 + fused BN stats --------------
__global__ void conv0_kernel(const float* __restrict__ x, const float* __restrict__ w0) {
    __shared__ float ws[108];
    __shared__ float r1[256], r2[256];
    int co = blockIdx.y, b = blockIdx.z;
    if (threadIdx.x < 108) ws[threadIdx.x] = w0[co * 108 + threadIdx.x];
    __syncthreads();
    int s = blockIdx.x * 256 + threadIdx.x;
    int z = s >> 10, y = (s >> 5) & 31, xx = s & 31;
    float acc = 0.f;
    #pragma unroll
    for (int ci = 0; ci < 4; ci++) {
        const float* xb = x + ((size_t)(b * 4 + ci) << 15);
        const float* wc = ws + ci * 27;
        #pragma unroll
        for (int kd = 0; kd < 3; kd++) {
            int id = z + kd - 1;
            if ((unsigned)id > 31u) continue;
            #pragma unroll
            for (int kh = 0; kh < 3; kh++) {
                int ih = y + kh - 1;
                if ((unsigned)ih > 31u) continue;
                #pragma unroll
                for (int kw = 0; kw < 3; kw++) {
                    int iw = xx + kw - 1;
                    if ((unsigned)iw > 31u) continue;
                    acc = fmaf(xb[(id << 10) + (ih << 5) + iw], wc[kd * 9 + kh * 3 + kw], acc);
                }
            }
        }
    }
    g_f0[(((size_t)((b << 8) + co)) << 15) + s] = acc;
    int tid = threadIdx.x;
    r1[tid] = acc; r2[tid] = acc * acc; __syncthreads();
    for (int o = 128; o; o >>= 1) {
        if (tid < o) { r1[tid] += r1[tid + o]; r2[tid] += r2[tid + o]; }
        __syncthreads();
    }
    if (tid == 0) {
        atomicAdd(&g_cs[co],  r1[0]);
        atomicAdd(&g_cs2[co], r2[0]);
    }
}

// bn+relu+transpose: f0 (b,c,s) fp32 -> f0h (b,s,c/2) fp16x2
__global__ void bn0_tr_kernel(const float* __restrict__ gm, const float* __restrict__ bt) {
    __shared__ float tile[32][33];
    __shared__ float scw[32], shw[32];
    int b = blockIdx.z, c0 = blockIdx.y * 32, s0 = blockIdx.x * 32;
    int x = threadIdx.x, y = threadIdx.y;      // 32 x 8
    if (y == 0) {
        int c = c0 + x;
        float inv = 1.f / 65536.f;
        float mean = g_cs[c] * inv;
        float var  = g_cs2[c] * inv - mean * mean;
        float sc = gm[c] * rsqrtf(var + 1e-5f);
        scw[x] = sc; shw[x] = bt[c] - mean * sc;
    }
    __syncthreads();
    for (int i = y; i < 32; i += 8) {
        float v = g_f0[(((size_t)((b << 8) + c0 + i)) << 15) + s0 + x];
        tile[i][x] = fmaxf(v * scw[i] + shw[i], 0.f);
    }
    __syncthreads();
    if (x < 16) {
        for (int i = y; i < 32; i += 8) {
            int s = s0 + i;
            g_f0h[((size_t)(b << 15) + s) * 128 + (c0 >> 1) + x] =
                pack2(tile[2 * x][i], tile[2 * x + 1][i]);
        }
    }
}

__global__ void reset_cs() {
    int c = threadIdx.x + blockIdx.x * 256;   // 512
    g_cs[c] = 0.f; g_cs2[c] = 0.f;
}

// ------------------------- fast BN stats, layout (rows, 512) -------------------------
__global__ void bn_stats_fast(const float* __restrict__ x, int rows) {
    int tid = threadIdx.x;               // 0..127
    int rpb = rows / gridDim.x;
    int r0 = blockIdx.x * rpb;
    float a1x = 0.f, a1y = 0.f, a1z = 0.f, a1w = 0.f;
    float a2x = 0.f, a2y = 0.f, a2z = 0.f, a2w = 0.f;
    const float4* xr = (const float4*)x;
    for (int r = r0; r < r0 + rpb; r++) {
        float4 v = xr[(size_t)r * 128 + tid];
        a1x += v.x; a1y += v.y; a1z += v.z; a1w += v.w;
        a2x += v.x * v.x; a2y += v.y * v.y; a2z += v.z * v.z; a2w += v.w * v.w;
    }
    int c = tid * 4;
    atomicAdd(&g_cs[c + 0], a1x); atomicAdd(&g_cs2[c + 0], a2x);
    atomicAdd(&g_cs[c + 1], a1y); atomicAdd(&g_cs2[c + 1], a2y);
    atomicAdd(&g_cs[c + 2], a1z); atomicAdd(&g_cs2[c + 2], a2z);
    atomicAdd(&g_cs[c + 3], a1w); atomicAdd(&g_cs2[c + 3], a2w);
}

__global__ void bn_final_rc(const float* __restrict__ gm, const float* __restrict__ bt,
                            float invRows) {
    int c = blockIdx.x * 256 + threadIdx.x;   // 512
    float mean = g_cs[c] * invRows;
    float var  = g_cs2[c] * invRows - mean * mean;
    float sc = gm[c] * rsqrtf(var + 1e-5f);
    g_scale[c] = sc;
    g_shift[c] = bt[c] - mean * sc;
    g_cs[c] = 0.f; g_cs2[c] = 0.f;            // self-clean for next use
}

// bn-apply -> fp16x2, layout (rows, C) float4 in, uint2 out
__global__ void bn_apply_rc_h(const float* __restrict__ x, unsigned* __restrict__ o,
                              int C, int n4, int do_relu) {
    int i = blockIdx.x * blockDim.x + threadIdx.x;
    if (i >= n4) return;
    int c = (i * 4) % C;
    float4 v = ((const float4*)x)[i];
    v.x = v.x * g_scale[c]     + g_shift[c];
    v.y = v.y * g_scale[c + 1] + g_shift[c + 1];
    v.z = v.z * g_scale[c + 2] + g_shift[c + 2];
    v.w = v.w * g_scale[c + 3] + g_shift[c + 3];
    if (do_relu) {
        v.x = fmaxf(v.x, 0.f); v.y = fmaxf(v.y, 0.f);
        v.z = fmaxf(v.z, 0.f); v.w = fmaxf(v.w, 0.f);
    }
    uint2 u; u.x = pack2(v.x, v.y); u.y = pack2(v.z, v.w);
    ((uint2*)o)[i] = u;
}

// ------------------------- weight prep (fp16x2 packed along K) -------------------------
__global__ void pack_w1(const float* __restrict__ w1) {
    int i = blockIdx.x * blockDim.x + threadIdx.x;   // k2 * 512 + co, k2 < 8192
    if (i >= 8192 * 512) return;
    int k2 = i >> 9, co = i & 511;
    int r = k2 >> 7, ci = (k2 & 127) * 2;
    size_t base = (size_t)co * 16384 + (size_t)ci * 64 + r;
    g_w1p[i] = pack2(w1[base], w1[base + 64]);
}

__global__ void pack_w2(const float* __restrict__ w2) {
    int i = blockIdx.x * blockDim.x + threadIdx.x;   // k2 * 512 + co, k2 < 6912
    if (i >= 6912 * 512) return;
    int k2 = i >> 9, co = i & 511;
    int r = k2 >> 8, ci = (k2 & 255) * 2;
    size_t base = (size_t)co * 13824 + (size_t)ci * 27 + r;
    g_w2p[i] = pack2(w2[base], w2[base + 27]);
}

__global__ void pack_cols(const float* __restrict__ src, unsigned* __restrict__ dst,
                          int rowOff, int K2, int F, int off, int Nout) {
    int i = blockIdx.x * blockDim.x + threadIdx.x;
    if (i >= K2 * F) return;
    int k2 = i / F, f = i - k2 * F;
    float a = src[(size_t)(2 * k2 + rowOff) * F + f];
    float b = src[(size_t)(2 * k2 + 1 + rowOff) * F + f];
    dst[(size_t)k2 * Nout + off + f] = pack2(a, b);
}

__global__ void copy_rows(const float* __restrict__ src, float* __restrict__ dst,
                          int rows, int F, int off, int Nout) {
    int i = blockIdx.x * blockDim.x + threadIdx.x;
    if (i >= rows * F) return;
    int k = i / F, f = i - k * F;
    dst[(size_t)k * Nout + off + f] = src[(size_t)k * F + f];
}

__global__ void build_bias(const float* __restrict__ src, float* __restrict__ dst,
                           int off, int F, int Nout) {
    int i = blockIdx.x * blockDim.x + threadIdx.x;
    if (i >= Nout) return;
    dst[i] = (i >= off && i < off + F) ? src[i - off] : 0.f;
}

// ------------------------- CSR build -------------------------
__global__ void hist_kernel(const int* __restrict__ ei) {
    int j = blockIdx.x * blockDim.x + threadIdx.x;
    if (j >= NE2) return;
    int b = (j >= NEDGES) ? 1 : 0;
    int e = j - b * NEDGES;
    int dst = __ldg(ei + NEDGES + e) + b * NNODES;
    atomicAdd(&g_deg[dst], 1);
}

__global__ void scan1_kernel() {
    __shared__ int tmp[1024];
    int tid = threadIdx.x;
    int gid = blockIdx.x * 1024 + tid;
    int v = (gid < NTOT) ? g_deg[gid] : 0;
    g_deg[gid] = 0;                      // self-clean
    tmp[tid] = v;
    __syncthreads();
    for (int o = 1; o < 1024; o <<= 1) {
        int t = (tid >= o) ? tmp[tid - o] : 0;
        __syncthreads();
        tmp[tid] += t;
        __syncthreads();
    }
    g_scan[gid] = tmp[tid] - v;
    if (tid == 1023) g_bsum[blockIdx.x] = tmp[1023];
}

__global__ void scan2_kernel() {
    if (threadIdx.x == 0) {
        int run = 0;
        for (int i = 0; i < SCAN_B; i++) { int t = g_bsum[i]; g_bsum[i] = run; run += t; }
        g_off[NTOT] = NE2;
    }
}

__global__ void scan3_kernel() {
    int gid = blockIdx.x * 1024 + threadIdx.x;
    if (gid >= NTOT) return;
    int o = g_scan[gid] + g_bsum[blockIdx.x];
    g_off[gid] = o;
    g_cur[gid] = o;
}

__global__ void fill_kernel(const int* __restrict__ ei) {
    int j = blockIdx.x * blockDim.x + threadIdx.x;
    if (j >= NE2) return;
    int b = (j >= NEDGES) ? 1 : 0;
    int e = j - b * NEDGES;
    int src = __ldg(ei + e) + b * NNODES;
    int dst = __ldg(ei + NEDGES + e) + b * NNODES;
    int pos = atomicAdd(&g_cur[dst], 1);
    g_srcs[pos] = src;
}

// -------- fp16 tensor-core GEMM (m16n8k16, 128x128 tile, cp.async 2-stage, 2 CTAs/SM) ----
// im2col modes use contiguous 16-word half-rows (one spatial tap) -> cpa16 like MODE 0.
// OUTH=0: fp32 C. OUTH=1: C fp16x2-packed (N/2 words per row).
#define ASD(s,m,k) sA[(s) * 4608 + (m) * 36 + (k)]
#define BSD(s,k,n) sB[(s) * 4352 + (k) * 136 + (n)]
template<int MODE, int OUTH>
__global__ void __launch_bounds__(256, 2)
mma_gemm(const unsigned* __restrict__ A, const unsigned* __restrict__ Bm,
         float* __restrict__ C, int M, int N, int K2, int lda,
         const float* __restrict__ bias, int do_relu) {
    extern __shared__ unsigned sm_raw[];
    unsigned* sA = sm_raw;            // 2 * 128 * 36
    unsigned* sB = sm_raw + 9216;     // 2 * 32 * 136
    int tid = threadIdx.x;
    int bm = blockIdx.y * 128, bn = blockIdx.x * 128;
    int warp = tid >> 5, lane = tid & 31;
    int wm = warp & 3, wn = warp >> 2;
    int g = lane >> 2, t4 = lane & 3;

    float c[2][8][4];
    #pragma unroll
    for (int i = 0; i < 2; i++)
        #pragma unroll
        for (int j = 0; j < 8; j++)
            #pragma unroll
            for (int r = 0; r < 4; r++) c[i][j][r] = 0.f;

    int ntiles = K2 >> 5;

    auto load_tile = [&](int s, int k0) {
        // ---- A: one contiguous 16-word (64B) half-row per thread ----
        {
            int m = tid >> 1, half = tid & 1;
            int gm = bm + m;
            int gk2 = k0 + half * 16;
            const unsigned* src = A;
            bool ok = false;
            if (MODE == 0) {
                ok = gm < M;
                src = A + (size_t)gm * lda + gk2;
            } else if (MODE == 1) {
                int b = gm >> 12, ss = gm & 4095;
                int od = ss >> 8, oh = (ss >> 4) & 15, ow = ss & 15;
                int r = gk2 >> 7, cc2 = gk2 & 127;
                int kd = r >> 4, kh = (r >> 2) & 3, kw = r & 3;
                int id = od * 2 - 1 + kd, ih = oh * 2 - 1 + kh, iw = ow * 2 - 1 + kw;
                ok = (unsigned)id <= 31u && (unsigned)ih <= 31u && (unsigned)iw <= 31u;
                src = A + ((size_t)((b << 15) + (id << 10) + (ih << 5) + iw)) * 128 + cc2;
            } else {
                int b = gm >> 12, ss = gm & 4095;
                int od = ss >> 8, oh = (ss >> 4) & 15, ow = ss & 15;
                int r = gk2 >> 8, cc2 = gk2 & 255;
                int kd = r / 9; int r2 = r - kd * 9;
                int kh = r2 / 3; int kw = r2 - kh * 3;
                int id = od - 1 + kd, ih = oh - 1 + kh, iw = ow - 1 + kw;
                ok = (unsigned)id <= 15u && (unsigned)ih <= 15u && (unsigned)iw <= 15u;
                src = A + ((size_t)((b << 12) + (id << 8) + (ih << 4) + iw)) * 256 + cc2;
            }
            int kof = half * 16;
            cpa16(&ASD(s, m, kof),      ok ? (src)      : A, ok);
            cpa16(&ASD(s, m, kof + 4),  ok ? (src + 4)  : A, ok);
            cpa16(&ASD(s, m, kof + 8),  ok ? (src + 8)  : A, ok);
            cpa16(&ASD(s, m, kof + 12), ok ? (src + 12) : A, ok);
        }
        // ---- B ----
        {
            int kk = tid >> 3, quad = tid & 7;
            const unsigned* brow = Bm + (size_t)(k0 + kk) * N + bn;
            #pragma unroll
            for (int i = 0; i < 4; i++) {
                int n = quad * 16 + i * 4;
                bool ok = (bn + n) < N;
                cpa16(&BSD(s, kk, n), ok ? (brow + n) : Bm, ok);
            }
        }
        asm volatile("cp.async.commit_group;\n");
    };

    load_tile(0, 0);
    for (int t = 0; t < ntiles; t++) {
        int s = t & 1;
        if (t + 1 < ntiles) {
            load_tile(s ^ 1, (t + 1) << 5);
            asm volatile("cp.async.wait_group 1;\n");
        } else {
            asm volatile("cp.async.wait_group 0;\n");
        }
        __syncthreads();
        #pragma unroll
        for (int ks = 0; ks < 4; ks++) {
            int kb2 = ks * 8;
            unsigned a[2][4];
            #pragma unroll
            for (int mt = 0; mt < 2; mt++) {
                int m0 = wm * 32 + mt * 16;
                a[mt][0] = ASD(s, m0 + g,     kb2 + t4);
                a[mt][1] = ASD(s, m0 + g + 8, kb2 + t4);
                a[mt][2] = ASD(s, m0 + g,     kb2 + t4 + 4);
                a[mt][3] = ASD(s, m0 + g + 8, kb2 + t4 + 4);
            }
            #pragma unroll
            for (int nt = 0; nt < 8; nt++) {
                int n0 = wn * 64 + nt * 8;
                unsigned b0 = BSD(s, kb2 + t4,     n0 + g);
                unsigned b1 = BSD(s, kb2 + t4 + 4, n0 + g);
                #pragma unroll
                for (int mt = 0; mt < 2; mt++) {
                    asm volatile(
                        "mma.sync.aligned.m16n8k16.row.col.f32.f16.f16.f32 "
                        "{%0,%1,%2,%3}, {%4,%5,%6,%7}, {%8,%9}, {%0,%1,%2,%3};"
                        : "+f"(c[mt][nt][0]), "+f"(c[mt][nt][1]),
                          "+f"(c[mt][nt][2]), "+f"(c[mt][nt][3])
                        : "r"(a[mt][0]), "r"(a[mt][1]), "r"(a[mt][2]), "r"(a[mt][3]),
                          "r"(b0), "r"(b1));
                }
            }
        }
        __syncthreads();
    }
    #pragma unroll
    for (int mt = 0; mt < 2; mt++) {
        #pragma unroll
        for (int nt = 0; nt < 8; nt++) {
            int gn0 = bn + wn * 64 + nt * 8 + 2 * t4;
            if (OUTH) {
                #pragma unroll
                for (int h = 0; h < 2; h++) {
                    int gm = bm + wm * 32 + mt * 16 + g + h * 8;
                    if (gm < M) {
                        float v0 = c[mt][nt][h * 2 + 0];
                        float v1 = c[mt][nt][h * 2 + 1];
                        if (bias) { v0 += bias[gn0]; v1 += bias[gn0 + 1]; }
                        if (do_relu) { v0 = fmaxf(v0, 0.f); v1 = fmaxf(v1, 0.f); }
                        ((unsigned*)C)[(size_t)gm * (N >> 1) + (gn0 >> 1)] = pack2(v0, v1);
                    }
                }
            } else {
                #pragma unroll
                for (int r = 0; r < 4; r++) {
                    int gm = bm + wm * 32 + mt * 16 + g + (r >> 1) * 8;
                    int gn = gn0 + (r & 1);
                    if (gm < M && gn < N) {
                        float v = c[mt][nt][r];
                        if (bias) v += bias[gn];
                        if (do_relu) v = fmaxf(v, 0.f);
                        C[(size_t)gm * N + gn] = v;
                    }
                }
            }
        }
    }
}

// ---------- per-node scatter: kqvs1h = pack(voxout[vox] + pos*Wpos + bias) -------------
__global__ void knode_kernel(const float* __restrict__ pos) {
    int r = blockIdx.x;
    int b = r / NNODES, n = r - b * NNODES;
    float p0 = pos[n * 3], p1 = pos[n * 3 + 1], p2 = pos[n * 3 + 2];
    int i0 = (int)(p0 * 16.f - 1.f);
    int i1 = (int)(p1 * 16.f - 1.f);
    int i2 = (int)(p2 * 16.f - 1.f);
    int vox = (i0 << 8) + (i1 << 4) + i2;
    const float4* vrow = (const float4*)(g_voxout + ((size_t)((b << 12) + vox)) * 1024);
    const float4* wr0  = (const float4*)(g_wpos1);
    const float4* wr1  = (const float4*)(g_wpos1 + 1024);
    const float4* wr2  = (const float4*)(g_wpos1 + 2048);
    const float4* br   = (const float4*)(g_bias1);
    uint2* drow = (uint2*)(g_kqvs1h + (size_t)r * 512);
    int c = threadIdx.x;                 // 0..255, 4 channels each
    float4 v = vrow[c], w0 = wr0[c], w1 = wr1[c], w2 = wr2[c], bb = br[c];
    float4 o;
    o.x = v.x + p0 * w0.x + p1 * w1.x + p2 * w2.x + bb.x;
    o.y = v.y + p0 * w0.y + p1 * w1.y + p2 * w2.y + bb.y;
    o.z = v.z + p0 * w0.z + p1 * w1.z + p2 * w2.z + bb.z;
    o.w = v.w + p0 * w0.w + p1 * w1.w + p2 * w2.w + bb.w;
    uint2 u; u.x = pack2(o.x, o.y); u.y = pack2(o.z, o.w);
    drow[c] = u;
}

// --------- CSR gated aggregation on fp16x2 rows + relu + fp16x2 pack (F/2 threads) --------
template<int F>
__global__ void agg_kernel(const unsigned* __restrict__ base, unsigned* __restrict__ packed) {
    int node = blockIdx.x;
    int t = threadIdx.x;                 // 0 .. F/2-1
    const int strideW = 2 * F;
    const int seg = F / 2;
    const unsigned* nrow = base + (size_t)node * strideW;
    float2 kv  = unpack2(nrow[t]);
    float2 acc = unpack2(nrow[3 * seg + t]);
    int s0 = __ldg(&g_off[node]), s1 = __ldg(&g_off[node + 1]);
    int i = s0;
    for (; i + 1 < s1; i += 2) {
        int srcA = __ldg(&g_srcs[i]);
        int srcB = __ldg(&g_srcs[i + 1]);
        const unsigned* rA = base + (size_t)srcA * strideW;
        const unsigned* rB = base + (size_t)srcB * strideW;
        float2 qA = unpack2(rA[seg + t]), vA = unpack2(rA[2 * seg + t]);
        float2 qB = unpack2(rB[seg + t]), vB = unpack2(rB[2 * seg + t]);
        acc.x += vA.x * (1.f / (1.f + __expf(-(kv.x + qA.x))));
        acc.y += vA.y * (1.f / (1.f + __expf(-(kv.y + qA.y))));
        acc.x += vB.x * (1.f / (1.f + __expf(-(kv.x + qB.x))));
        acc.y += vB.y * (1.f / (1.f + __expf(-(kv.y + qB.y))));
    }
    if (i < s1) {
        int src = __ldg(&g_srcs[i]);
        const unsigned* rr = base + (size_t)src * strideW;
        float2 q = unpack2(rr[seg + t]), v = unpack2(rr[2 * seg + t]);
        acc.x += v.x * (1.f / (1.f + __expf(-(kv.x + q.x))));
        acc.y += v.y * (1.f / (1.f + __expf(-(kv.y + q.y))));
    }
    packed[(size_t)node * seg + t] = pack2(fmaxf(acc.x, 0.f), fmaxf(acc.y, 0.f));
}

// ------------------------- final tiny layer (N=3) -------------------------
__global__ void mlp2_kernel(const float* __restrict__ w, const float* __restrict__ bb,
                            float* __restrict__ out) {
    int r = blockIdx.x * blockDim.x + threadIdx.x;
    if (r >= NTOT) return;
    const float* row = g_h3 + (size_t)r * 64;
    float a0 = bb[0], a1 = bb[1], a2 = bb[2];
    #pragma unroll
    for (int k = 0; k < 64; k++) {
        float xv = row[k];
        a0 = fmaf(xv, __ldg(&w[k * 3 + 0]), a0);
        a1 = fmaf(xv, __ldg(&w[k * 3 + 1]), a1);
        a2 = fmaf(xv, __ldg(&w[k * 3 + 2]), a2);
    }
    out[r * 3 + 0] = fmaxf(a0, 0.f);
    out[r * 3 + 1] = fmaxf(a1, 0.f);
    out[r * 3 + 2] = fmaxf(a2, 0.f);
}

// ------------------------- launcher -------------------------
extern "C" void kernel_launch(void* const* d_in, const int* in_sizes, int n_in,
                              void* d_out, int out_size) {
    const float* x   = (const float*)d_in[0];
    const float* pos = (const float*)d_in[1];
    const float* w0  = (const float*)d_in[2];
    const float* g0  = (const float*)d_in[3];
    const float* b0  = (const float*)d_in[4];
    const float* w1  = (const float*)d_in[5];
    const float* g1  = (const float*)d_in[6];
    const float* b1  = (const float*)d_in[7];
    const float* w2  = (const float*)d_in[8];
    const float* g2  = (const float*)d_in[9];
    const float* b2  = (const float*)d_in[10];
    const float* gk1 = (const float*)d_in[11];
    const float* gq1 = (const float*)d_in[12];
    const float* gv1 = (const float*)d_in[13];
    const float* gs1 = (const float*)d_in[14];
    const float* gb1 = (const float*)d_in[15];
    const float* gk2 = (const float*)d_in[16];
    const float* gq2 = (const float*)d_in[17];
    const float* gv2 = (const float*)d_in[18];
    const float* gs2 = (const float*)d_in[19];
    const float* gb2 = (const float*)d_in[20];
    const float* m1w = (const float*)d_in[21];
    const float* m1b = (const float*)d_in[22];
    const float* m2w = (const float*)d_in[23];
    const float* m2b = (const float*)d_in[24];
    const int*   ei  = (const int*)d_in[25];
    float* out = (float*)d_out;

    float    *p_f1, *p_f2, *p_wpos1, *p_bias1, *p_bias2;
    float    *p_voxout, *p_h3;
    unsigned *p_f0h, *p_f1h, *p_f2h, *p_w1p, *p_w2p, *p_wfeat1p, *p_wcat2p, *p_m1wp;
    unsigned *p_kqvs1h, *p_kqvs2h, *p_h1h, *p_h2h;
    cudaGetSymbolAddress((void**)&p_f0h,     g_f0h);
    cudaGetSymbolAddress((void**)&p_f1,      g_f1);
    cudaGetSymbolAddress((void**)&p_f1h,     g_f1h);
    cudaGetSymbolAddress((void**)&p_f2,      g_f2);
    cudaGetSymbolAddress((void**)&p_f2h,     g_f2h);
    cudaGetSymbolAddress((void**)&p_w1p,     g_w1p);
    cudaGetSymbolAddress((void**)&p_w2p,     g_w2p);
    cudaGetSymbolAddress((void**)&p_wfeat1p, g_wfeat1p);
    cudaGetSymbolAddress((void**)&p_wpos1,   g_wpos1);
    cudaGetSymbolAddress((void**)&p_bias1,   g_bias1);
    cudaGetSymbolAddress((void**)&p_wcat2p,  g_wcat2p);
    cudaGetSymbolAddress((void**)&p_bias2,   g_bias2);
    cudaGetSymbolAddress((void**)&p_m1wp,    g_m1wp);
    cudaGetSymbolAddress((void**)&p_voxout,  g_voxout);
    cudaGetSymbolAddress((void**)&p_kqvs1h,  g_kqvs1h);
    cudaGetSymbolAddress((void**)&p_h1h,     g_h1h);
    cudaGetSymbolAddress((void**)&p_kqvs2h,  g_kqvs2h);
    cudaGetSymbolAddress((void**)&p_h2h,     g_h2h);
    cudaGetSymbolAddress((void**)&p_h3,      g_h3);

    cudaFuncSetAttribute(mma_gemm<0, 0>, cudaFuncAttributeMaxDynamicSharedMemorySize, SMEM_BYTES);
    cudaFuncSetAttribute(mma_gemm<0, 1>, cudaFuncAttributeMaxDynamicSharedMemorySize, SMEM_BYTES);
    cudaFuncSetAttribute(mma_gemm<1, 0>, cudaFuncAttributeMaxDynamicSharedMemorySize, SMEM_BYTES);
    cudaFuncSetAttribute(mma_gemm<2, 0>, cudaFuncAttributeMaxDynamicSharedMemorySize, SMEM_BYTES);

    // -------- launches 1..4: keep the big conv1 GEMM at slot 4 (profiler samples it) ----
    pack_w1<<<CDIV(8192 * 512, 256), 256>>>(w1);                                        // 1
    conv0_kernel<<<dim3(128, 256, 2), 256>>>(x, w0);                                    // 2
    bn0_tr_kernel<<<dim3(1024, 8, 2), dim3(32, 8)>>>(g0, b0);                           // 3
    mma_gemm<1, 0><<<dim3(4, 64), 256, SMEM_BYTES>>>(p_f0h, p_w1p, p_f1,                // 4
                                                     8192, 512, 8192, 0, nullptr, 0);

    // reset conv0 stat accumulators (before conv1 stats accumulate)
    reset_cs<<<2, 256>>>();

    // conv1 bn -> fp16
    bn_stats_fast<<<256, 128>>>(p_f1, 8192);
    bn_final_rc<<<2, 256>>>(g1, b1, 1.f / 8192.f);
    bn_apply_rc_h<<<CDIV(1048576, 256), 256>>>(p_f1, p_f1h, 512, 1048576, 1);

    // conv2 + bn -> fp16
    pack_w2<<<CDIV(6912 * 512, 256), 256>>>(w2);
    mma_gemm<2, 0><<<dim3(4, 64), 256, SMEM_BYTES>>>(p_f1h, p_w2p, p_f2, 8192, 512, 6912, 0, nullptr, 0);
    bn_stats_fast<<<256, 128>>>(p_f2, 8192);
    bn_final_rc<<<2, 256>>>(g2, b2, 1.f / 8192.f);
    bn_apply_rc_h<<<CDIV(1048576, 256), 256>>>(p_f2, p_f2h, 512, 1048576, 0);

    // CSR build
    hist_kernel<<<CDIV(NE2, 256), 256>>>(ei);
    scan1_kernel<<<SCAN_B, 1024>>>();
    scan2_kernel<<<1, 32>>>();
    scan3_kernel<<<SCAN_B, 1024>>>();
    fill_kernel<<<CDIV(NE2, 256), 256>>>(ei);

    // GNN weight prep (fp16x2 packed)
    pack_cols<<<CDIV(256 * 256, 256), 256>>>(gk1, p_wfeat1p, 3, 256, 256, 0,    1024);
    pack_cols<<<CDIV(256 * 256, 256), 256>>>(gq1, p_wfeat1p, 3, 256, 256, 256,  1024);
    pack_cols<<<CDIV(256 * 256, 256), 256>>>(gv1, p_wfeat1p, 3, 256, 256, 512,  1024);
    pack_cols<<<CDIV(256 * 256, 256), 256>>>(gs1, p_wfeat1p, 3, 256, 256, 768,  1024);
    copy_rows<<<3, 256>>>(gk1, p_wpos1, 3, 256, 0,   1024);
    copy_rows<<<3, 256>>>(gq1, p_wpos1, 3, 256, 256, 1024);
    copy_rows<<<3, 256>>>(gv1, p_wpos1, 3, 256, 512, 1024);
    copy_rows<<<3, 256>>>(gs1, p_wpos1, 3, 256, 768, 1024);
    pack_cols<<<CDIV(128 * 128, 256), 256>>>(gk2, p_wcat2p, 0, 128, 128, 0,   512);
    pack_cols<<<CDIV(128 * 128, 256), 256>>>(gq2, p_wcat2p, 0, 128, 128, 128, 512);
    pack_cols<<<CDIV(128 * 128, 256), 256>>>(gv2, p_wcat2p, 0, 128, 128, 256, 512);
    pack_cols<<<CDIV(128 * 128, 256), 256>>>(gs2, p_wcat2p, 0, 128, 128, 384, 512);
    pack_cols<<<CDIV(64 * 64, 256), 256>>>(m1w, p_m1wp, 0, 64, 64, 0, 64);
    build_bias<<<4, 256>>>(gb1, p_bias1, 768, 256, 1024);
    build_bias<<<2, 256>>>(gb2, p_bias2, 384, 128, 512);

    // voxel-level GNN1 GEMM: (8192, K2=256) @ (256, 1024) -> fp32 voxout
    mma_gemm<0, 0><<<dim3(8, 64), 256, SMEM_BYTES>>>(p_f2h, p_wfeat1p, p_voxout,
                                                     8192, 1024, 256, 256, nullptr, 0);
    knode_kernel<<<NTOT, 256>>>(pos);

    // GNN layer 1: CSR aggregation (fp16 rows) + relu + pack
    agg_kernel<256><<<NTOT, 128>>>(p_kqvs1h, p_h1h);

    // GNN layer 2: (100000, K2=128) @ (128, 512) -> fp16 packed kqvs2h (+bias2)
    mma_gemm<0, 1><<<dim3(4, CDIV(NTOT, 128)), 256, SMEM_BYTES>>>(
        p_h1h, p_wcat2p, (float*)p_kqvs2h, NTOT, 512, 128, 128, p_bias2, 0);
    agg_kernel<128><<<NTOT, 64>>>(p_kqvs2h, p_h2h);

    // MLP head: (100000, K2=64) @ (64, 64) -> fp32 h3
    mma_gemm<0, 0><<<dim3(1, CDIV(NTOT, 128)), 256, SMEM_BYTES>>>(p_h2h, p_m1wp, p_h3,
                                                                  NTOT, 64, 64, 64, m1b, 1);
    mlp2_kernel<<<CDIV(NTOT, 256), 256>>>(m2w, m2b, out);
}